// round 3
// baseline (speedup 1.0000x reference)
#include <cuda_runtime.h>
#include <cuda_bf16.h>
#include <cstdint>

#define HDIM 128

// ---------------- static scratch (no allocations allowed) ----------------
#define NA_MAX 50000
#define NB_MAX 30000
#define EA_MAX 600000
#define EB_MAX 300000

__device__ float g_bufA0[NA_MAX * HDIM];
__device__ float g_bufA1[NA_MAX * HDIM];
__device__ float g_bufB0[NB_MAX * HDIM];
__device__ float g_bufB1[NB_MAX * HDIM];

__device__ int g_cntOutA[NA_MAX];
__device__ int g_cntInA[NA_MAX];
__device__ int g_fillA[NA_MAX];
__device__ int g_rowpA[NA_MAX + 1];
__device__ int g_colA[EA_MAX];
__device__ float g_nsA[NA_MAX];
__device__ float g_ndA[NA_MAX];

__device__ int g_cntOutB[NB_MAX];
__device__ int g_cntInB[NB_MAX];
__device__ int g_fillB[NB_MAX];
__device__ int g_rowpB[NB_MAX + 1];
__device__ int g_colB[EB_MAX];
__device__ float g_nsB[NB_MAX];
__device__ float g_ndB[NB_MAX];

// ---------------- f32x2 packed helpers (sm_10x FFMA2 path) ----------------
__device__ __forceinline__ unsigned long long pack2_dup(float x) {
    unsigned long long r;
    asm("mov.b64 %0, {%1, %1};" : "=l"(r) : "f"(x));
    return r;
}
__device__ __forceinline__ unsigned long long fma2(unsigned long long a,
                                                   unsigned long long b,
                                                   unsigned long long c) {
    unsigned long long d;
    asm("fma.rn.f32x2 %0, %1, %2, %3;" : "=l"(d) : "l"(a), "l"(b), "l"(c));
    return d;
}
__device__ __forceinline__ float2 unpack2(unsigned long long v) {
    float2 f;
    asm("mov.b64 {%0, %1}, %2;" : "=f"(f.x), "=f"(f.y) : "l"(v));
    return f;
}

// ---------------- small graph-prep kernels ----------------
__global__ void zero_int_kernel(int* p, int n) {
    int i = blockIdx.x * blockDim.x + threadIdx.x;
    if (i < n) p[i] = 0;
}

__global__ void count_deg_kernel(const int* __restrict__ src, const int* __restrict__ dst,
                                 int E, int* cntOut, int* cntIn) {
    int i = blockIdx.x * blockDim.x + threadIdx.x;
    if (i < E) {
        atomicAdd(&cntOut[src[i]], 1);
        atomicAdd(&cntIn[dst[i]], 1);
    }
}

__global__ void norms_kernel(const int* __restrict__ cntOut, const int* __restrict__ cntIn,
                             float* ns, float* nd, int n) {
    int i = blockIdx.x * blockDim.x + threadIdx.x;
    if (i < n) {
        ns[i] = rsqrtf((float)(cntOut[i] + 1));  // +1 self loop
        nd[i] = rsqrtf((float)(cntIn[i] + 1));
    }
}

// Single-block exclusive scan of cnt[0..n) -> rowp[0..n], rowp[0]=0.
__global__ void scan_kernel(const int* __restrict__ cnt, int* rowp, int n) {
    __shared__ int sh[1024];
    __shared__ int carry;
    if (threadIdx.x == 0) { carry = 0; rowp[0] = 0; }
    __syncthreads();
    for (int base = 0; base < n; base += 1024) {
        int i = base + threadIdx.x;
        int v = (i < n) ? cnt[i] : 0;
        sh[threadIdx.x] = v;
        __syncthreads();
        for (int off = 1; off < 1024; off <<= 1) {
            int t = (threadIdx.x >= off) ? sh[threadIdx.x - off] : 0;
            __syncthreads();
            sh[threadIdx.x] += t;
            __syncthreads();
        }
        if (i < n) rowp[i + 1] = carry + sh[threadIdx.x];
        __syncthreads();
        if (threadIdx.x == 0) carry += sh[1023];
        __syncthreads();
    }
}

__global__ void csr_fill_kernel(const int* __restrict__ src, const int* __restrict__ dst,
                                int E, const int* __restrict__ rowp, int* fill, int* col) {
    int i = blockIdx.x * blockDim.x + threadIdx.x;
    if (i < E) {
        int d = dst[i];
        int pos = atomicAdd(&fill[d], 1);
        col[rowp[d] + pos] = src[i];
    }
}

// ---------------- SGEMM: Y[M,128] = (X[M,K] * ns[row]) @ W[K,128] ----------------
// BM=128, BN=128, BK=16, double-buffered smem, 256 threads, 8x8 microtile,
// FFMA2 (f32x2) accumulation paired along N.
__global__ __launch_bounds__(256) void sgemm_scaled_kernel(
    const float* __restrict__ X, const float* __restrict__ ns,
    const float* __restrict__ W, float* __restrict__ Y,
    int M, int K) {
    __shared__ float As[2][16][128];   // As[buf][k][row]
    __shared__ float Bs[2][16][128];   // Bs[buf][k][col]

    const int tid = threadIdx.x;
    const int block_row = blockIdx.x * 128;
    const int ty = tid >> 4;   // 0..15 -> rows ty*8..+7
    const int tx = tid & 15;   // 0..15 -> cols tx*8..+7

    // A-load mapping: row_a = tid/2 (0..127), 8 cols starting at (tid&1)*8
    const int row_a = tid >> 1;
    const int ca = (tid & 1) * 8;
    // B-load mapping: row_b = tid/16 (0..15), 8 cols at (tid&15)*8
    const int row_b = tid >> 4;
    const int cb = (tid & 15) * 8;

    const int grow = block_row + row_a;
    const bool arow_ok = (grow < M);
    const float ascale = arow_ok ? ns[grow] : 0.0f;
    const float* Xrow = X + (size_t)grow * K;

    unsigned long long acc[8][4];
    #pragma unroll
    for (int i = 0; i < 8; i++)
        #pragma unroll
        for (int j = 0; j < 4; j++) acc[i][j] = 0ULL;

    const int nt = K >> 4;

    // ---- load tile 0 directly into smem buffer 0 ----
    {
        float4 a0 = make_float4(0.f, 0.f, 0.f, 0.f), a1 = a0;
        if (arow_ok) {
            a0 = *(const float4*)&Xrow[ca];
            a1 = *(const float4*)&Xrow[ca + 4];
        }
        As[0][ca + 0][row_a] = a0.x * ascale;
        As[0][ca + 1][row_a] = a0.y * ascale;
        As[0][ca + 2][row_a] = a0.z * ascale;
        As[0][ca + 3][row_a] = a0.w * ascale;
        As[0][ca + 4][row_a] = a1.x * ascale;
        As[0][ca + 5][row_a] = a1.y * ascale;
        As[0][ca + 6][row_a] = a1.z * ascale;
        As[0][ca + 7][row_a] = a1.w * ascale;
        *(float4*)&Bs[0][row_b][cb]     = *(const float4*)&W[(size_t)row_b * HDIM + cb];
        *(float4*)&Bs[0][row_b][cb + 4] = *(const float4*)&W[(size_t)row_b * HDIM + cb + 4];
    }
    __syncthreads();

    for (int t = 0; t < nt; t++) {
        const int cur = t & 1;
        const int nxt = cur ^ 1;
        const bool has_next = (t + 1 < nt);

        // prefetch next tile into registers
        float4 pa0 = make_float4(0.f, 0.f, 0.f, 0.f), pa1 = pa0, pb0, pb1;
        if (has_next) {
            const int k0 = (t + 1) << 4;
            if (arow_ok) {
                pa0 = *(const float4*)&Xrow[k0 + ca];
                pa1 = *(const float4*)&Xrow[k0 + ca + 4];
            }
            pb0 = *(const float4*)&W[(size_t)(k0 + row_b) * HDIM + cb];
            pb1 = *(const float4*)&W[(size_t)(k0 + row_b) * HDIM + cb + 4];
        }

        // compute on current buffer
        #pragma unroll
        for (int k = 0; k < 16; k++) {
            float4 a0 = *(const float4*)&As[cur][k][ty * 8];
            float4 a1 = *(const float4*)&As[cur][k][ty * 8 + 4];
            ulonglong2 bb0 = *(const ulonglong2*)&Bs[cur][k][tx * 8];
            ulonglong2 bb1 = *(const ulonglong2*)&Bs[cur][k][tx * 8 + 4];
            unsigned long long rb[4] = {bb0.x, bb0.y, bb1.x, bb1.y};
            float ra[8] = {a0.x, a0.y, a0.z, a0.w, a1.x, a1.y, a1.z, a1.w};
            #pragma unroll
            for (int i = 0; i < 8; i++) {
                unsigned long long rad = pack2_dup(ra[i]);
                #pragma unroll
                for (int j = 0; j < 4; j++)
                    acc[i][j] = fma2(rad, rb[j], acc[i][j]);
            }
        }

        if (has_next) {
            As[nxt][ca + 0][row_a] = pa0.x * ascale;
            As[nxt][ca + 1][row_a] = pa0.y * ascale;
            As[nxt][ca + 2][row_a] = pa0.z * ascale;
            As[nxt][ca + 3][row_a] = pa0.w * ascale;
            As[nxt][ca + 4][row_a] = pa1.x * ascale;
            As[nxt][ca + 5][row_a] = pa1.y * ascale;
            As[nxt][ca + 6][row_a] = pa1.z * ascale;
            As[nxt][ca + 7][row_a] = pa1.w * ascale;
            *(float4*)&Bs[nxt][row_b][cb]     = pb0;
            *(float4*)&Bs[nxt][row_b][cb + 4] = pb1;
            __syncthreads();
        }
    }

    // epilogue
    #pragma unroll
    for (int i = 0; i < 8; i++) {
        int gr = block_row + ty * 8 + i;
        if (gr < M) {
            float2 p0 = unpack2(acc[i][0]);
            float2 p1 = unpack2(acc[i][1]);
            float2 p2 = unpack2(acc[i][2]);
            float2 p3 = unpack2(acc[i][3]);
            float4 o0 = make_float4(p0.x, p0.y, p1.x, p1.y);
            float4 o1 = make_float4(p2.x, p2.y, p3.x, p3.y);
            *(float4*)&Y[(size_t)gr * HDIM + tx * 8]     = o0;
            *(float4*)&Y[(size_t)gr * HDIM + tx * 8 + 4] = o1;
        }
    }
}

// ---------------- aggregation: out[i] = relu?((y[i] + sum_nbr y[nbr]) * nd[i] + b) ----------------
__global__ __launch_bounds__(256) void aggregate_kernel(
    const float* __restrict__ y,
    const int* __restrict__ rowp, const int* __restrict__ col,
    const float* __restrict__ nd, const float* __restrict__ bias,
    float* __restrict__ out, int n, int do_relu) {
    int warp = (blockIdx.x * blockDim.x + threadIdx.x) >> 5;
    int lane = threadIdx.x & 31;
    if (warp >= n) return;

    const float4* yrow = (const float4*)(y + (size_t)warp * HDIM);
    float4 acc = yrow[lane];  // self loop

    int s = __ldg(&rowp[warp]);
    int e = __ldg(&rowp[warp + 1]);
    for (int i = s; i < e; i++) {
        int nb = __ldg(&col[i]);
        float4 v = *((const float4*)(y + (size_t)nb * HDIM) + lane);
        acc.x += v.x; acc.y += v.y; acc.z += v.z; acc.w += v.w;
    }
    float sc = nd[warp];
    float4 b = ((const float4*)bias)[lane];
    float4 r;
    r.x = fmaf(acc.x, sc, b.x);
    r.y = fmaf(acc.y, sc, b.y);
    r.z = fmaf(acc.z, sc, b.z);
    r.w = fmaf(acc.w, sc, b.w);
    if (do_relu) {
        r.x = fmaxf(r.x, 0.f); r.y = fmaxf(r.y, 0.f);
        r.z = fmaxf(r.z, 0.f); r.w = fmaxf(r.w, 0.f);
    }
    ((float4*)(out + (size_t)warp * HDIM))[lane] = r;
}

// ---------------- host orchestration ----------------
static inline int cdiv(int a, int b) { return (a + b - 1) / b; }

extern "C" void kernel_launch(void* const* d_in, const int* in_sizes, int n_in,
                              void* d_out, int out_size) {
    const float* feat_a = (const float*)d_in[0];
    const float* feat_b = (const float*)d_in[1];
    const int* src_a = (const int*)d_in[2];
    const int* dst_a = (const int*)d_in[3];
    const int* src_b = (const int*)d_in[4];
    const int* dst_b = (const int*)d_in[5];
    const float* Wa0 = (const float*)d_in[6];
    const float* ba0 = (const float*)d_in[7];
    const float* Wa1 = (const float*)d_in[8];
    const float* ba1 = (const float*)d_in[9];
    const float* Wb0 = (const float*)d_in[10];
    const float* bb0 = (const float*)d_in[11];
    const float* Wb1 = (const float*)d_in[12];
    const float* bb1 = (const float*)d_in[13];

    const int H = in_sizes[7];                 // 128
    const int DA = in_sizes[6] / H;            // 256
    const int NA = in_sizes[0] / DA;           // 50000
    const int EA = in_sizes[2];                // 600000
    const int DB = in_sizes[10] / H;           // 128
    const int NB = in_sizes[1] / DB;           // 30000
    const int EB = in_sizes[4];                // 300000

    float* out = (float*)d_out;
    float* out_a = out;
    float* out_b = out + (size_t)NA * HDIM;

    // resolve device-global scratch (non-stream API; capture-safe)
    float *bufA0, *bufA1, *bufB0, *bufB1, *nsA, *ndA, *nsB, *ndB;
    int *cntOutA, *cntInA, *fillA, *rowpA, *colA;
    int *cntOutB, *cntInB, *fillB, *rowpB, *colB;
    cudaGetSymbolAddress((void**)&bufA0, g_bufA0);
    cudaGetSymbolAddress((void**)&bufA1, g_bufA1);
    cudaGetSymbolAddress((void**)&bufB0, g_bufB0);
    cudaGetSymbolAddress((void**)&bufB1, g_bufB1);
    cudaGetSymbolAddress((void**)&nsA, g_nsA);
    cudaGetSymbolAddress((void**)&ndA, g_ndA);
    cudaGetSymbolAddress((void**)&nsB, g_nsB);
    cudaGetSymbolAddress((void**)&ndB, g_ndB);
    cudaGetSymbolAddress((void**)&cntOutA, g_cntOutA);
    cudaGetSymbolAddress((void**)&cntInA, g_cntInA);
    cudaGetSymbolAddress((void**)&fillA, g_fillA);
    cudaGetSymbolAddress((void**)&rowpA, g_rowpA);
    cudaGetSymbolAddress((void**)&colA, g_colA);
    cudaGetSymbolAddress((void**)&cntOutB, g_cntOutB);
    cudaGetSymbolAddress((void**)&cntInB, g_cntInB);
    cudaGetSymbolAddress((void**)&fillB, g_fillB);
    cudaGetSymbolAddress((void**)&rowpB, g_rowpB);
    cudaGetSymbolAddress((void**)&colB, g_colB);

    const int T = 256;

    // ---- graph prep A ----
    zero_int_kernel<<<cdiv(NA, T), T>>>(cntOutA, NA);
    zero_int_kernel<<<cdiv(NA, T), T>>>(cntInA, NA);
    zero_int_kernel<<<cdiv(NA, T), T>>>(fillA, NA);
    count_deg_kernel<<<cdiv(EA, T), T>>>(src_a, dst_a, EA, cntOutA, cntInA);
    norms_kernel<<<cdiv(NA, T), T>>>(cntOutA, cntInA, nsA, ndA, NA);
    scan_kernel<<<1, 1024>>>(cntInA, rowpA, NA);
    csr_fill_kernel<<<cdiv(EA, T), T>>>(src_a, dst_a, EA, rowpA, fillA, colA);

    // ---- graph prep B ----
    zero_int_kernel<<<cdiv(NB, T), T>>>(cntOutB, NB);
    zero_int_kernel<<<cdiv(NB, T), T>>>(cntInB, NB);
    zero_int_kernel<<<cdiv(NB, T), T>>>(fillB, NB);
    count_deg_kernel<<<cdiv(EB, T), T>>>(src_b, dst_b, EB, cntOutB, cntInB);
    norms_kernel<<<cdiv(NB, T), T>>>(cntOutB, cntInB, nsB, ndB, NB);
    scan_kernel<<<1, 1024>>>(cntInB, rowpB, NB);
    csr_fill_kernel<<<cdiv(EB, T), T>>>(src_b, dst_b, EB, rowpB, fillB, colB);

    // ---- ntype A ----
    sgemm_scaled_kernel<<<cdiv(NA, 128), 256>>>(feat_a, nsA, Wa0, bufA0, NA, DA);
    aggregate_kernel<<<cdiv(NA * 32, 256), 256>>>(bufA0, rowpA, colA, ndA, ba0, bufA1, NA, 1);
    sgemm_scaled_kernel<<<cdiv(NA, 128), 256>>>(bufA1, nsA, Wa1, bufA0, NA, H);
    aggregate_kernel<<<cdiv(NA * 32, 256), 256>>>(bufA0, rowpA, colA, ndA, ba1, out_a, NA, 0);

    // ---- ntype B ----
    sgemm_scaled_kernel<<<cdiv(NB, 128), 256>>>(feat_b, nsB, Wb0, bufB0, NB, DB);
    aggregate_kernel<<<cdiv(NB * 32, 256), 256>>>(bufB0, rowpB, colB, ndB, bb0, bufB1, NB, 1);
    sgemm_scaled_kernel<<<cdiv(NB, 128), 256>>>(bufB1, nsB, Wb1, bufB0, NB, H);
    aggregate_kernel<<<cdiv(NB * 32, 256), 256>>>(bufB0, rowpB, colB, ndB, bb1, out_b, NB, 0);

    (void)n_in; (void)out_size;
}

// round 4
// speedup vs baseline: 1.4978x; 1.4978x over previous
#include <cuda_runtime.h>
#include <cuda_bf16.h>
#include <cstdint>

#define HDIM 128

// ---------------- static scratch ----------------
#define NA_MAX 50000
#define NB_MAX 30000
#define EA_MAX 600000
#define EB_MAX 300000

__device__ __nv_bfloat16 g_XhiA[NA_MAX * 256];
__device__ __nv_bfloat16 g_XloA[NA_MAX * 256];
__device__ float g_YA[NA_MAX * HDIM];
__device__ __nv_bfloat16 g_XhiB[NB_MAX * HDIM];
__device__ __nv_bfloat16 g_XloB[NB_MAX * HDIM];
__device__ float g_YB[NB_MAX * HDIM];
__device__ __nv_bfloat16 g_Whi[256 * HDIM];   // transposed [N][K]
__device__ __nv_bfloat16 g_Wlo[256 * HDIM];

__device__ int g_cntOutA[NA_MAX];
__device__ int g_cntInA[NA_MAX];
__device__ int g_fillA[NA_MAX];
__device__ int g_rowpA[NA_MAX + 1];
__device__ int g_colA[EA_MAX];
__device__ float g_nsA[NA_MAX];
__device__ float g_ndA[NA_MAX];

__device__ int g_cntOutB[NB_MAX];
__device__ int g_cntInB[NB_MAX];
__device__ int g_fillB[NB_MAX];
__device__ int g_rowpB[NB_MAX + 1];
__device__ int g_colB[EB_MAX];
__device__ float g_nsB[NB_MAX];
__device__ float g_ndB[NB_MAX];

// ---------------- graph-prep kernels ----------------
__global__ void zero_int_kernel(int* p, int n) {
    int i = blockIdx.x * blockDim.x + threadIdx.x;
    if (i < n) p[i] = 0;
}

__global__ void count_deg_kernel(const int* __restrict__ src, const int* __restrict__ dst,
                                 int E, int* cntOut, int* cntIn) {
    int i = blockIdx.x * blockDim.x + threadIdx.x;
    if (i < E) {
        atomicAdd(&cntOut[src[i]], 1);
        atomicAdd(&cntIn[dst[i]], 1);
    }
}

__global__ void norms_kernel(const int* __restrict__ cntOut, const int* __restrict__ cntIn,
                             float* ns, float* nd, int n) {
    int i = blockIdx.x * blockDim.x + threadIdx.x;
    if (i < n) {
        ns[i] = rsqrtf((float)(cntOut[i] + 1));
        nd[i] = rsqrtf((float)(cntIn[i] + 1));
    }
}

// shuffle-based exclusive scan, single block
__global__ void scan_kernel(const int* __restrict__ cnt, int* rowp, int n) {
    __shared__ int warpsum[32];
    __shared__ int carry_s;
    const int tid = threadIdx.x;
    const int lane = tid & 31;
    const int wid = tid >> 5;
    if (tid == 0) { carry_s = 0; rowp[0] = 0; }
    __syncthreads();
    for (int base = 0; base < n; base += 1024) {
        int i = base + tid;
        int v = (i < n) ? cnt[i] : 0;
        int x = v;
        #pragma unroll
        for (int d = 1; d < 32; d <<= 1) {
            int y = __shfl_up_sync(0xFFFFFFFFu, x, d);
            if (lane >= d) x += y;
        }
        if (lane == 31) warpsum[wid] = x;
        __syncthreads();
        if (wid == 0) {
            int w = warpsum[lane];
            #pragma unroll
            for (int d = 1; d < 32; d <<= 1) {
                int y = __shfl_up_sync(0xFFFFFFFFu, w, d);
                if (lane >= d) w += y;
            }
            warpsum[lane] = w;
        }
        __syncthreads();
        int off = carry_s + (wid ? warpsum[wid - 1] : 0);
        if (i < n) rowp[i + 1] = off + x;
        __syncthreads();
        if (tid == 0) carry_s += warpsum[31];
        __syncthreads();
    }
}

__global__ void csr_fill_kernel(const int* __restrict__ src, const int* __restrict__ dst,
                                int E, const int* __restrict__ rowp, int* fill, int* col) {
    int i = blockIdx.x * blockDim.x + threadIdx.x;
    if (i < E) {
        int d = dst[i];
        int pos = atomicAdd(&fill[d], 1);
        col[rowp[d] + pos] = src[i];
    }
}

// ---------------- bf16 split helpers ----------------
__device__ __forceinline__ void split_bf16(float v, __nv_bfloat16& hi, __nv_bfloat16& lo) {
    hi = __float2bfloat16(v);
    lo = __float2bfloat16(v - __bfloat162float(hi));
}

// feat conversion: Xhi/Xlo = split(X * ns[row]); thread per float4
__global__ void convert_feat_kernel(const float* __restrict__ X, const float* __restrict__ ns,
                                    __nv_bfloat16* __restrict__ Xhi, __nv_bfloat16* __restrict__ Xlo,
                                    int nquads, int kqshift) {
    int q = blockIdx.x * blockDim.x + threadIdx.x;
    if (q >= nquads) return;
    int row = q >> kqshift;
    float s = ns[row];
    float4 v = ((const float4*)X)[q];
    union { ushort4 u; __nv_bfloat16 b[4]; } H, L;
    split_bf16(v.x * s, H.b[0], L.b[0]);
    split_bf16(v.y * s, H.b[1], L.b[1]);
    split_bf16(v.z * s, H.b[2], L.b[2]);
    split_bf16(v.w * s, H.b[3], L.b[3]);
    ((ushort4*)Xhi)[q] = H.u;
    ((ushort4*)Xlo)[q] = L.u;
}

// W conversion + transpose: Wt[n][k] = split(W[k][n]); N == 128
__global__ void convW_kernel(const float* __restrict__ W,
                             __nv_bfloat16* __restrict__ Whi, __nv_bfloat16* __restrict__ Wlo,
                             int K) {
    int idx = blockIdx.x * blockDim.x + threadIdx.x;
    if (idx >= K * HDIM) return;
    int k = idx >> 7;
    int n = idx & 127;
    __nv_bfloat16 hi, lo;
    split_bf16(W[idx], hi, lo);
    Whi[n * K + k] = hi;
    Wlo[n * K + k] = lo;
}

// ---------------- bf16-split tensor-core GEMM ----------------
// Y[M,128] = Xhi@Whi + Xhi@Wlo + Xlo@Whi  (fp32 accum)
// CTA: 128x128, 8 warps (2x4), warp tile 64x32, BK=32.
__device__ __forceinline__ void mma_bf16(float& d0, float& d1, float& d2, float& d3,
                                         unsigned a0, unsigned a1, unsigned a2, unsigned a3,
                                         unsigned b0, unsigned b1) {
    asm volatile(
        "mma.sync.aligned.m16n8k16.row.col.f32.bf16.bf16.f32 "
        "{%0,%1,%2,%3}, {%4,%5,%6,%7}, {%8,%9}, {%0,%1,%2,%3};"
        : "+f"(d0), "+f"(d1), "+f"(d2), "+f"(d3)
        : "r"(a0), "r"(a1), "r"(a2), "r"(a3), "r"(b0), "r"(b1));
}

#define SPAD 40  // 32 + 8 pad (80B row -> conflict-free fragment loads)

__global__ __launch_bounds__(256) void gemm_bf16_kernel(
    const __nv_bfloat16* __restrict__ Ahi, const __nv_bfloat16* __restrict__ Alo,
    const __nv_bfloat16* __restrict__ Bhi, const __nv_bfloat16* __restrict__ Blo,  // [128][K]
    float* __restrict__ Y, int M, int K) {
    __shared__ __nv_bfloat16 sAhi[128][SPAD];
    __shared__ __nv_bfloat16 sAlo[128][SPAD];
    __shared__ __nv_bfloat16 sBhi[128][SPAD];
    __shared__ __nv_bfloat16 sBlo[128][SPAD];

    const int tid = threadIdx.x;
    const int wid = tid >> 5;
    const int lane = tid & 31;
    const int g = lane >> 2;   // group 0..7
    const int tg = lane & 3;   // thread-in-group
    const int warpM = wid >> 2;   // 0..1
    const int warpN = wid & 3;    // 0..3
    const int block_row = blockIdx.x * 128;

    float acc[4][4][4];
    #pragma unroll
    for (int i = 0; i < 4; i++)
        #pragma unroll
        for (int j = 0; j < 4; j++)
            #pragma unroll
            for (int c = 0; c < 4; c++) acc[i][j][c] = 0.0f;

    // G2S mapping: 16B units; unit u: row = u>>2, kc = (u&3)*8; 512 units, 2/thread
    const int r0 = tid >> 2,          kc0 = (tid & 3) * 8;
    const int r1 = (tid + 256) >> 2,  kc1 = kc0;  // (tid+256)&3 == tid&3

    for (int k0 = 0; k0 < K; k0 += 32) {
        {
            int gr0 = block_row + r0;
            int gr1 = block_row + r1;
            uint4 z = make_uint4(0, 0, 0, 0);
            uint4 ah0 = (gr0 < M) ? *(const uint4*)&Ahi[(size_t)gr0 * K + k0 + kc0] : z;
            uint4 al0 = (gr0 < M) ? *(const uint4*)&Alo[(size_t)gr0 * K + k0 + kc0] : z;
            uint4 ah1 = (gr1 < M) ? *(const uint4*)&Ahi[(size_t)gr1 * K + k0 + kc1] : z;
            uint4 al1 = (gr1 < M) ? *(const uint4*)&Alo[(size_t)gr1 * K + k0 + kc1] : z;
            uint4 bh0 = *(const uint4*)&Bhi[(size_t)r0 * K + k0 + kc0];
            uint4 bl0 = *(const uint4*)&Blo[(size_t)r0 * K + k0 + kc0];
            uint4 bh1 = *(const uint4*)&Bhi[(size_t)r1 * K + k0 + kc1];
            uint4 bl1 = *(const uint4*)&Blo[(size_t)r1 * K + k0 + kc1];
            *(uint4*)&sAhi[r0][kc0] = ah0;
            *(uint4*)&sAlo[r0][kc0] = al0;
            *(uint4*)&sAhi[r1][kc1] = ah1;
            *(uint4*)&sAlo[r1][kc1] = al1;
            *(uint4*)&sBhi[r0][kc0] = bh0;
            *(uint4*)&sBlo[r0][kc0] = bl0;
            *(uint4*)&sBhi[r1][kc1] = bh1;
            *(uint4*)&sBlo[r1][kc1] = bl1;
        }
        __syncthreads();

        #pragma unroll
        for (int kk = 0; kk < 32; kk += 16) {
            // B fragments (hi & lo) for 4 n-tiles
            unsigned bh[4][2], bl[4][2];
            #pragma unroll
            for (int nt = 0; nt < 4; nt++) {
                const __nv_bfloat16* pb = &sBhi[warpN * 32 + nt * 8 + g][kk + tg * 2];
                bh[nt][0] = *(const unsigned*)pb;
                bh[nt][1] = *(const unsigned*)(pb + 8);
                const __nv_bfloat16* pl = &sBlo[warpN * 32 + nt * 8 + g][kk + tg * 2];
                bl[nt][0] = *(const unsigned*)pl;
                bl[nt][1] = *(const unsigned*)(pl + 8);
            }
            #pragma unroll
            for (int mt = 0; mt < 4; mt++) {
                const __nv_bfloat16* pa = &sAhi[warpM * 64 + mt * 16 + g][kk + tg * 2];
                unsigned a0 = *(const unsigned*)pa;
                unsigned a1 = *(const unsigned*)(pa + 8 * SPAD);
                unsigned a2 = *(const unsigned*)(pa + 8);
                unsigned a3 = *(const unsigned*)(pa + 8 * SPAD + 8);
                #pragma unroll
                for (int nt = 0; nt < 4; nt++) {
                    mma_bf16(acc[mt][nt][0], acc[mt][nt][1], acc[mt][nt][2], acc[mt][nt][3],
                             a0, a1, a2, a3, bh[nt][0], bh[nt][1]);
                    mma_bf16(acc[mt][nt][0], acc[mt][nt][1], acc[mt][nt][2], acc[mt][nt][3],
                             a0, a1, a2, a3, bl[nt][0], bl[nt][1]);
                }
                const __nv_bfloat16* pal = &sAlo[warpM * 64 + mt * 16 + g][kk + tg * 2];
                unsigned l0 = *(const unsigned*)pal;
                unsigned l1 = *(const unsigned*)(pal + 8 * SPAD);
                unsigned l2 = *(const unsigned*)(pal + 8);
                unsigned l3 = *(const unsigned*)(pal + 8 * SPAD + 8);
                #pragma unroll
                for (int nt = 0; nt < 4; nt++) {
                    mma_bf16(acc[mt][nt][0], acc[mt][nt][1], acc[mt][nt][2], acc[mt][nt][3],
                             l0, l1, l2, l3, bh[nt][0], bh[nt][1]);
                }
            }
        }
        __syncthreads();
    }

    // epilogue: fp32 store
    #pragma unroll
    for (int mt = 0; mt < 4; mt++) {
        #pragma unroll
        for (int nt = 0; nt < 4; nt++) {
            int r = block_row + warpM * 64 + mt * 16 + g;
            int c = warpN * 32 + nt * 8 + tg * 2;
            if (r < M) {
                float2 v0 = make_float2(acc[mt][nt][0], acc[mt][nt][1]);
                *(float2*)&Y[(size_t)r * HDIM + c] = v0;
            }
            if (r + 8 < M) {
                float2 v1 = make_float2(acc[mt][nt][2], acc[mt][nt][3]);
                *(float2*)&Y[(size_t)(r + 8) * HDIM + c] = v1;
            }
        }
    }
}

// ---------------- aggregation ----------------
// mode 1 (mid layer): r = relu((self+sum)*nd + b); write split(r*ns) -> hi/lo bf16
// mode 0 (final):     r = (self+sum)*nd + b;        write f32 -> out_f32
__global__ __launch_bounds__(256) void aggregate_kernel(
    const float* __restrict__ y,
    const int* __restrict__ rowp, const int* __restrict__ col,
    const float* __restrict__ nd, const float* __restrict__ ns,
    const float* __restrict__ bias,
    float* __restrict__ out_f32,
    __nv_bfloat16* __restrict__ out_hi, __nv_bfloat16* __restrict__ out_lo,
    int n, int mode) {
    int warp = (blockIdx.x * blockDim.x + threadIdx.x) >> 5;
    int lane = threadIdx.x & 31;
    if (warp >= n) return;

    const float4* yrow = (const float4*)(y + (size_t)warp * HDIM);
    float4 acc = yrow[lane];  // self loop

    int s = __ldg(&rowp[warp]);
    int e = __ldg(&rowp[warp + 1]);
    for (int i = s; i < e; i++) {
        int nb = __ldg(&col[i]);
        float4 v = *((const float4*)(y + (size_t)nb * HDIM) + lane);
        acc.x += v.x; acc.y += v.y; acc.z += v.z; acc.w += v.w;
    }
    float sc = nd[warp];
    float4 b = ((const float4*)bias)[lane];
    float4 r;
    r.x = fmaf(acc.x, sc, b.x);
    r.y = fmaf(acc.y, sc, b.y);
    r.z = fmaf(acc.z, sc, b.z);
    r.w = fmaf(acc.w, sc, b.w);
    if (mode) {
        r.x = fmaxf(r.x, 0.f); r.y = fmaxf(r.y, 0.f);
        r.z = fmaxf(r.z, 0.f); r.w = fmaxf(r.w, 0.f);
        float nsv = ns[warp];
        union { ushort4 u; __nv_bfloat16 bb[4]; } H, L;
        split_bf16(r.x * nsv, H.bb[0], L.bb[0]);
        split_bf16(r.y * nsv, H.bb[1], L.bb[1]);
        split_bf16(r.z * nsv, H.bb[2], L.bb[2]);
        split_bf16(r.w * nsv, H.bb[3], L.bb[3]);
        *(ushort4*)&out_hi[(size_t)warp * HDIM + lane * 4] = H.u;
        *(ushort4*)&out_lo[(size_t)warp * HDIM + lane * 4] = L.u;
    } else {
        ((float4*)(out_f32 + (size_t)warp * HDIM))[lane] = r;
    }
}

// ---------------- host orchestration ----------------
static inline int cdiv(int a, int b) { return (a + b - 1) / b; }

extern "C" void kernel_launch(void* const* d_in, const int* in_sizes, int n_in,
                              void* d_out, int out_size) {
    const float* feat_a = (const float*)d_in[0];
    const float* feat_b = (const float*)d_in[1];
    const int* src_a = (const int*)d_in[2];
    const int* dst_a = (const int*)d_in[3];
    const int* src_b = (const int*)d_in[4];
    const int* dst_b = (const int*)d_in[5];
    const float* Wa0 = (const float*)d_in[6];
    const float* ba0 = (const float*)d_in[7];
    const float* Wa1 = (const float*)d_in[8];
    const float* ba1 = (const float*)d_in[9];
    const float* Wb0 = (const float*)d_in[10];
    const float* bb0 = (const float*)d_in[11];
    const float* Wb1 = (const float*)d_in[12];
    const float* bb1 = (const float*)d_in[13];

    const int H = in_sizes[7];                 // 128
    const int DA = in_sizes[6] / H;            // 256
    const int NA = in_sizes[0] / DA;           // 50000
    const int EA = in_sizes[2];                // 600000
    const int DB = in_sizes[10] / H;           // 128
    const int NB = in_sizes[1] / DB;           // 30000
    const int EB = in_sizes[4];                // 300000

    float* out = (float*)d_out;
    float* out_a = out;
    float* out_b = out + (size_t)NA * HDIM;

    __nv_bfloat16 *XhiA, *XloA, *XhiB, *XloB, *Whi, *Wlo;
    float *YA, *YB, *nsA, *ndA, *nsB, *ndB;
    int *cntOutA, *cntInA, *fillA, *rowpA, *colA;
    int *cntOutB, *cntInB, *fillB, *rowpB, *colB;
    cudaGetSymbolAddress((void**)&XhiA, g_XhiA);
    cudaGetSymbolAddress((void**)&XloA, g_XloA);
    cudaGetSymbolAddress((void**)&YA, g_YA);
    cudaGetSymbolAddress((void**)&XhiB, g_XhiB);
    cudaGetSymbolAddress((void**)&XloB, g_XloB);
    cudaGetSymbolAddress((void**)&YB, g_YB);
    cudaGetSymbolAddress((void**)&Whi, g_Whi);
    cudaGetSymbolAddress((void**)&Wlo, g_Wlo);
    cudaGetSymbolAddress((void**)&nsA, g_nsA);
    cudaGetSymbolAddress((void**)&ndA, g_ndA);
    cudaGetSymbolAddress((void**)&nsB, g_nsB);
    cudaGetSymbolAddress((void**)&ndB, g_ndB);
    cudaGetSymbolAddress((void**)&cntOutA, g_cntOutA);
    cudaGetSymbolAddress((void**)&cntInA, g_cntInA);
    cudaGetSymbolAddress((void**)&fillA, g_fillA);
    cudaGetSymbolAddress((void**)&rowpA, g_rowpA);
    cudaGetSymbolAddress((void**)&colA, g_colA);
    cudaGetSymbolAddress((void**)&cntOutB, g_cntOutB);
    cudaGetSymbolAddress((void**)&cntInB, g_cntInB);
    cudaGetSymbolAddress((void**)&fillB, g_fillB);
    cudaGetSymbolAddress((void**)&rowpB, g_rowpB);
    cudaGetSymbolAddress((void**)&colB, g_colB);

    const int T = 256;

    // ===== ntype A =====
    zero_int_kernel<<<cdiv(NA, T), T>>>(cntOutA, NA);
    zero_int_kernel<<<cdiv(NA, T), T>>>(cntInA, NA);
    count_deg_kernel<<<cdiv(EA, T), T>>>(src_a, dst_a, EA, cntOutA, cntInA);
    norms_kernel<<<cdiv(NA, T), T>>>(cntOutA, cntInA, nsA, ndA, NA);

    // layer 0 GEMM inputs
    convW_kernel<<<cdiv(DA * H, T), T>>>(Wa0, Whi, Wlo, DA);
    {
        int nq = NA * DA / 4;
        int kqshift = (DA == 256) ? 6 : 5;
        convert_feat_kernel<<<cdiv(nq, T), T>>>(feat_a, nsA, XhiA, XloA, nq, kqshift);
    }
    gemm_bf16_kernel<<<cdiv(NA, 128), 256>>>(XhiA, XloA, Whi, Wlo, YA, NA, DA);

    // CSR for A
    zero_int_kernel<<<cdiv(NA, T), T>>>(fillA, NA);
    scan_kernel<<<1, 1024>>>(cntInA, rowpA, NA);
    csr_fill_kernel<<<cdiv(EA, T), T>>>(src_a, dst_a, EA, rowpA, fillA, colA);

    // layer 0 aggregate -> bf16 hi/lo (scaled by ns, relu)
    aggregate_kernel<<<cdiv(NA * 32, 256), 256>>>(YA, rowpA, colA, ndA, nsA, ba0,
                                                  nullptr, XhiA, XloA, NA, 1);
    // layer 1
    convW_kernel<<<cdiv(H * H, T), T>>>(Wa1, Whi, Wlo, H);
    gemm_bf16_kernel<<<cdiv(NA, 128), 256>>>(XhiA, XloA, Whi, Wlo, YA, NA, H);
    aggregate_kernel<<<cdiv(NA * 32, 256), 256>>>(YA, rowpA, colA, ndA, nsA, ba1,
                                                  out_a, nullptr, nullptr, NA, 0);

    // ===== ntype B =====
    zero_int_kernel<<<cdiv(NB, T), T>>>(cntOutB, NB);
    zero_int_kernel<<<cdiv(NB, T), T>>>(cntInB, NB);
    count_deg_kernel<<<cdiv(EB, T), T>>>(src_b, dst_b, EB, cntOutB, cntInB);
    norms_kernel<<<cdiv(NB, T), T>>>(cntOutB, cntInB, nsB, ndB, NB);

    convW_kernel<<<cdiv(DB * H, T), T>>>(Wb0, Whi, Wlo, DB);
    {
        int nq = NB * DB / 4;
        int kqshift = (DB == 256) ? 6 : 5;
        convert_feat_kernel<<<cdiv(nq, T), T>>>(feat_b, nsB, XhiB, XloB, nq, kqshift);
    }
    gemm_bf16_kernel<<<cdiv(NB, 128), 256>>>(XhiB, XloB, Whi, Wlo, YB, NB, DB);

    zero_int_kernel<<<cdiv(NB, T), T>>>(fillB, NB);
    scan_kernel<<<1, 1024>>>(cntInB, rowpB, NB);
    csr_fill_kernel<<<cdiv(EB, T), T>>>(src_b, dst_b, EB, rowpB, fillB, colB);

    aggregate_kernel<<<cdiv(NB * 32, 256), 256>>>(YB, rowpB, colB, ndB, nsB, bb0,
                                                  nullptr, XhiB, XloB, NB, 1);
    convW_kernel<<<cdiv(H * H, T), T>>>(Wb1, Whi, Wlo, H);
    gemm_bf16_kernel<<<cdiv(NB, 128), 256>>>(XhiB, XloB, Whi, Wlo, YB, NB, H);
    aggregate_kernel<<<cdiv(NB * 32, 256), 256>>>(YB, rowpB, colB, ndB, nsB, bb1,
                                                  out_b, nullptr, nullptr, NB, 0);

    (void)n_in; (void)out_size;
}

// round 5
// speedup vs baseline: 1.6971x; 1.1331x over previous
#include <cuda_runtime.h>
#include <cuda_bf16.h>
#include <cstdint>

#define HDIM 128
#define SPAD 40

// ---------------- static scratch ----------------
#define NA_MAX 50000
#define NB_MAX 30000
#define EA_MAX 600000
#define EB_MAX 300000

__device__ __nv_bfloat16 g_XhiA[NA_MAX * 256];
__device__ __nv_bfloat16 g_XloA[NA_MAX * 256];
__device__ float g_YA[NA_MAX * HDIM];
__device__ __nv_bfloat16 g_XhiB[NB_MAX * HDIM];
__device__ __nv_bfloat16 g_XloB[NB_MAX * HDIM];
__device__ float g_YB[NB_MAX * HDIM];
__device__ __nv_bfloat16 g_Whi[256 * HDIM];   // transposed [N][K]
__device__ __nv_bfloat16 g_Wlo[256 * HDIM];

__device__ int g_cntOutA[NA_MAX];
__device__ int g_cntInA[NA_MAX];
__device__ int g_fillA[NA_MAX];
__device__ int g_rowpA[NA_MAX + 1];
__device__ int g_colA[EA_MAX];
__device__ float g_nsA[NA_MAX];
__device__ float g_ndA[NA_MAX];

__device__ int g_cntOutB[NB_MAX];
__device__ int g_cntInB[NB_MAX];
__device__ int g_fillB[NB_MAX];
__device__ int g_rowpB[NB_MAX + 1];
__device__ int g_colB[EB_MAX];
__device__ float g_nsB[NB_MAX];
__device__ float g_ndB[NB_MAX];

// ---------------- graph-prep kernels ----------------
__global__ void zero_all_kernel(int* a0, int* a1, int* a2, int na,
                                int* b0, int* b1, int* b2, int nb) {
    int i = blockIdx.x * blockDim.x + threadIdx.x;
    if (i < na) { a0[i] = 0; a1[i] = 0; a2[i] = 0; }
    if (i < nb) { b0[i] = 0; b1[i] = 0; b2[i] = 0; }
}

__global__ void count_deg_kernel(const int* __restrict__ src, const int* __restrict__ dst,
                                 int E, int* cntOut, int* cntIn) {
    int i = blockIdx.x * blockDim.x + threadIdx.x;
    if (i < E) {
        atomicAdd(&cntOut[src[i]], 1);
        atomicAdd(&cntIn[dst[i]], 1);
    }
}

__global__ void norms_kernel(const int* __restrict__ cntOut, const int* __restrict__ cntIn,
                             float* ns, float* nd, int n) {
    int i = blockIdx.x * blockDim.x + threadIdx.x;
    if (i < n) {
        ns[i] = rsqrtf((float)(cntOut[i] + 1));
        nd[i] = rsqrtf((float)(cntIn[i] + 1));
    }
}

// shuffle-based exclusive scan, single block
__global__ void scan_kernel(const int* __restrict__ cnt, int* rowp, int n) {
    __shared__ int warpsum[32];
    __shared__ int carry_s;
    const int tid = threadIdx.x;
    const int lane = tid & 31;
    const int wid = tid >> 5;
    if (tid == 0) { carry_s = 0; rowp[0] = 0; }
    __syncthreads();
    for (int base = 0; base < n; base += 1024) {
        int i = base + tid;
        int v = (i < n) ? cnt[i] : 0;
        int x = v;
        #pragma unroll
        for (int d = 1; d < 32; d <<= 1) {
            int y = __shfl_up_sync(0xFFFFFFFFu, x, d);
            if (lane >= d) x += y;
        }
        if (lane == 31) warpsum[wid] = x;
        __syncthreads();
        if (wid == 0) {
            int w = warpsum[lane];
            #pragma unroll
            for (int d = 1; d < 32; d <<= 1) {
                int y = __shfl_up_sync(0xFFFFFFFFu, w, d);
                if (lane >= d) w += y;
            }
            warpsum[lane] = w;
        }
        __syncthreads();
        int off = carry_s + (wid ? warpsum[wid - 1] : 0);
        if (i < n) rowp[i + 1] = off + x;
        __syncthreads();
        if (tid == 0) carry_s += warpsum[31];
        __syncthreads();
    }
}

__global__ void csr_fill_kernel(const int* __restrict__ src, const int* __restrict__ dst,
                                int E, const int* __restrict__ rowp, int* fill, int* col) {
    int i = blockIdx.x * blockDim.x + threadIdx.x;
    if (i < E) {
        int d = dst[i];
        int pos = atomicAdd(&fill[d], 1);
        col[rowp[d] + pos] = src[i];
    }
}

// ---------------- bf16 split helpers ----------------
__device__ __forceinline__ void split_bf16(float v, __nv_bfloat16& hi, __nv_bfloat16& lo) {
    hi = __float2bfloat16(v);
    lo = __float2bfloat16(v - __bfloat162float(hi));
}

__global__ void convert_feat_kernel(const float* __restrict__ X, const float* __restrict__ ns,
                                    __nv_bfloat16* __restrict__ Xhi, __nv_bfloat16* __restrict__ Xlo,
                                    int nquads, int kqshift) {
    int q = blockIdx.x * blockDim.x + threadIdx.x;
    if (q >= nquads) return;
    int row = q >> kqshift;
    float s = ns[row];
    float4 v = ((const float4*)X)[q];
    union { ushort4 u; __nv_bfloat16 b[4]; } H, L;
    split_bf16(v.x * s, H.b[0], L.b[0]);
    split_bf16(v.y * s, H.b[1], L.b[1]);
    split_bf16(v.z * s, H.b[2], L.b[2]);
    split_bf16(v.w * s, H.b[3], L.b[3]);
    ((ushort4*)Xhi)[q] = H.u;
    ((ushort4*)Xlo)[q] = L.u;
}

__global__ void convW_kernel(const float* __restrict__ W,
                             __nv_bfloat16* __restrict__ Whi, __nv_bfloat16* __restrict__ Wlo,
                             int K) {
    int idx = blockIdx.x * blockDim.x + threadIdx.x;
    if (idx >= K * HDIM) return;
    int k = idx >> 7;
    int n = idx & 127;
    __nv_bfloat16 hi, lo;
    split_bf16(W[idx], hi, lo);
    Whi[n * K + k] = hi;
    Wlo[n * K + k] = lo;
}

// ---------------- MMA / LDSM / cp.async primitives ----------------
__device__ __forceinline__ void mma_bf16(float& d0, float& d1, float& d2, float& d3,
                                         unsigned a0, unsigned a1, unsigned a2, unsigned a3,
                                         unsigned b0, unsigned b1) {
    asm volatile(
        "mma.sync.aligned.m16n8k16.row.col.f32.bf16.bf16.f32 "
        "{%0,%1,%2,%3}, {%4,%5,%6,%7}, {%8,%9}, {%0,%1,%2,%3};"
        : "+f"(d0), "+f"(d1), "+f"(d2), "+f"(d3)
        : "r"(a0), "r"(a1), "r"(a2), "r"(a3), "r"(b0), "r"(b1));
}

__device__ __forceinline__ void ldsm4(uint32_t addr, unsigned& r0, unsigned& r1,
                                      unsigned& r2, unsigned& r3) {
    asm volatile("ldmatrix.sync.aligned.m8n8.x4.shared.b16 {%0,%1,%2,%3}, [%4];"
                 : "=r"(r0), "=r"(r1), "=r"(r2), "=r"(r3) : "r"(addr));
}

__device__ __forceinline__ void cp16(uint32_t smem_addr, const void* gmem, bool pred) {
    int sz = pred ? 16 : 0;
    asm volatile("cp.async.cg.shared.global [%0], [%1], 16, %2;"
                 :: "r"(smem_addr), "l"(gmem), "r"(sz));
}
__device__ __forceinline__ void cp_commit() {
    asm volatile("cp.async.commit_group;");
}
__device__ __forceinline__ void cp_wait1() {
    asm volatile("cp.async.wait_group 1;");
}

// ---------------- bf16-split tensor-core GEMM ----------------
// Y[M,128] = Xhi@Whi + Xhi@Wlo + Xlo@Whi  (fp32 accum)
// CTA 128x128, 8 warps (2x4), warp tile 64x32, BK=32,
// 2-stage cp.async pipeline, ldmatrix fragment loads.
#define STAGE_ELE (128 * SPAD)
#define STAGE_BYTES (STAGE_ELE * 2)
#define GEMM_SMEM (4 * 2 * STAGE_BYTES)  // 81920 B

__global__ __launch_bounds__(256) void gemm_bf16_kernel(
    const __nv_bfloat16* __restrict__ Ahi, const __nv_bfloat16* __restrict__ Alo,
    const __nv_bfloat16* __restrict__ Bhi, const __nv_bfloat16* __restrict__ Blo,  // [128][K]
    float* __restrict__ Y, int M, int K) {
    extern __shared__ __align__(16) char dynsmem[];
    __nv_bfloat16* sAhi = (__nv_bfloat16*)dynsmem;              // [2][128][SPAD]
    __nv_bfloat16* sAlo = sAhi + 2 * STAGE_ELE;
    __nv_bfloat16* sBhi = sAlo + 2 * STAGE_ELE;
    __nv_bfloat16* sBlo = sBhi + 2 * STAGE_ELE;

    const int tid = threadIdx.x;
    const int wid = tid >> 5;
    const int lane = tid & 31;
    const int warpM = wid >> 2;   // 0..1
    const int warpN = wid & 3;    // 0..3
    const int block_row = blockIdx.x * 128;

    float acc[4][4][4];
    #pragma unroll
    for (int i = 0; i < 4; i++)
        #pragma unroll
        for (int j = 0; j < 4; j++)
            #pragma unroll
            for (int c = 0; c < 4; c++) acc[i][j][c] = 0.0f;

    // G2S mapping: 512 16B-units per tile-array; unit u: row=u>>2, kcol=(u&3)*8
    const int r0 = tid >> 2, kc0 = (tid & 3) * 8;
    const int r1 = r0 + 64;
    const int gr0 = block_row + r0;
    const int gr1 = block_row + r1;
    const bool v0 = gr0 < M;
    const bool v1 = gr1 < M;

    const uint32_t bAhi = (uint32_t)__cvta_generic_to_shared(sAhi);
    const uint32_t bAlo = (uint32_t)__cvta_generic_to_shared(sAlo);
    const uint32_t bBhi = (uint32_t)__cvta_generic_to_shared(sBhi);
    const uint32_t bBlo = (uint32_t)__cvta_generic_to_shared(sBlo);

    const uint32_t st_off0 = (uint32_t)(r0 * SPAD + kc0) * 2;
    const uint32_t st_off1 = (uint32_t)(r1 * SPAD + kc0) * 2;

    // ldmatrix lane offsets (bytes within a stage)
    const int aRow = warpM * 64 + (lane & 15);
    const int aColOff = (lane >> 4) * 8;
    const uint32_t offA = (uint32_t)(aRow * SPAD + aColOff) * 2;
    const int bRow = warpN * 32 + ((lane >> 4) & 1) * 8 + (lane & 7);
    const int bColOff = ((lane >> 3) & 1) * 8;
    const uint32_t offB = (uint32_t)(bRow * SPAD + bColOff) * 2;

    const int ntiles = K >> 5;

    // prefetch tile 0 into stage 0
    {
        const int k0 = 0;
        cp16(bAhi + st_off0, &Ahi[(size_t)gr0 * K + k0 + kc0], v0);
        cp16(bAlo + st_off0, &Alo[(size_t)gr0 * K + k0 + kc0], v0);
        cp16(bAhi + st_off1, &Ahi[(size_t)gr1 * K + k0 + kc0], v1);
        cp16(bAlo + st_off1, &Alo[(size_t)gr1 * K + k0 + kc0], v1);
        cp16(bBhi + st_off0, &Bhi[(size_t)r0 * K + k0 + kc0], true);
        cp16(bBlo + st_off0, &Blo[(size_t)r0 * K + k0 + kc0], true);
        cp16(bBhi + st_off1, &Bhi[(size_t)r1 * K + k0 + kc0], true);
        cp16(bBlo + st_off1, &Blo[(size_t)r1 * K + k0 + kc0], true);
    }
    cp_commit();

    for (int t = 0; t < ntiles; t++) {
        if (t + 1 < ntiles) {
            const int k0 = (t + 1) << 5;
            const uint32_t sb = (uint32_t)((t + 1) & 1) * STAGE_BYTES;
            cp16(bAhi + sb + st_off0, &Ahi[(size_t)gr0 * K + k0 + kc0], v0);
            cp16(bAlo + sb + st_off0, &Alo[(size_t)gr0 * K + k0 + kc0], v0);
            cp16(bAhi + sb + st_off1, &Ahi[(size_t)gr1 * K + k0 + kc0], v1);
            cp16(bAlo + sb + st_off1, &Alo[(size_t)gr1 * K + k0 + kc0], v1);
            cp16(bBhi + sb + st_off0, &Bhi[(size_t)r0 * K + k0 + kc0], true);
            cp16(bBlo + sb + st_off0, &Blo[(size_t)r0 * K + k0 + kc0], true);
            cp16(bBhi + sb + st_off1, &Bhi[(size_t)r1 * K + k0 + kc0], true);
            cp16(bBlo + sb + st_off1, &Blo[(size_t)r1 * K + k0 + kc0], true);
        }
        cp_commit();
        cp_wait1();
        __syncthreads();

        const uint32_t sb = (uint32_t)(t & 1) * STAGE_BYTES;

        #pragma unroll
        for (int kk = 0; kk < 32; kk += 16) {
            // B fragments: hi & lo for 4 n-tiles (2 ldmatrix.x4 each)
            unsigned bh[4][2], bl[4][2];
            #pragma unroll
            for (int pair = 0; pair < 2; pair++) {
                const uint32_t ad = sb + offB + (uint32_t)(pair * 16 * SPAD + kk) * 2;
                ldsm4(bBhi + ad, bh[pair * 2][0], bh[pair * 2][1],
                      bh[pair * 2 + 1][0], bh[pair * 2 + 1][1]);
                ldsm4(bBlo + ad, bl[pair * 2][0], bl[pair * 2][1],
                      bl[pair * 2 + 1][0], bl[pair * 2 + 1][1]);
            }
            #pragma unroll
            for (int mt = 0; mt < 4; mt++) {
                const uint32_t ad = sb + offA + (uint32_t)(mt * 16 * SPAD + kk) * 2;
                unsigned a0, a1, a2, a3, l0, l1, l2, l3;
                ldsm4(bAhi + ad, a0, a1, a2, a3);
                ldsm4(bAlo + ad, l0, l1, l2, l3);
                #pragma unroll
                for (int nt = 0; nt < 4; nt++) {
                    mma_bf16(acc[mt][nt][0], acc[mt][nt][1], acc[mt][nt][2], acc[mt][nt][3],
                             a0, a1, a2, a3, bh[nt][0], bh[nt][1]);
                    mma_bf16(acc[mt][nt][0], acc[mt][nt][1], acc[mt][nt][2], acc[mt][nt][3],
                             a0, a1, a2, a3, bl[nt][0], bl[nt][1]);
                    mma_bf16(acc[mt][nt][0], acc[mt][nt][1], acc[mt][nt][2], acc[mt][nt][3],
                             l0, l1, l2, l3, bh[nt][0], bh[nt][1]);
                }
            }
        }
        __syncthreads();
    }

    // epilogue: fp32 store
    const int g = lane >> 2;
    const int tg = lane & 3;
    #pragma unroll
    for (int mt = 0; mt < 4; mt++) {
        #pragma unroll
        for (int nt = 0; nt < 4; nt++) {
            int r = block_row + warpM * 64 + mt * 16 + g;
            int c = warpN * 32 + nt * 8 + tg * 2;
            if (r < M) {
                float2 v0m = make_float2(acc[mt][nt][0], acc[mt][nt][1]);
                *(float2*)&Y[(size_t)r * HDIM + c] = v0m;
            }
            if (r + 8 < M) {
                float2 v1m = make_float2(acc[mt][nt][2], acc[mt][nt][3]);
                *(float2*)&Y[(size_t)(r + 8) * HDIM + c] = v1m;
            }
        }
    }
}

// ---------------- aggregation ----------------
__global__ __launch_bounds__(256) void aggregate_kernel(
    const float* __restrict__ y,
    const int* __restrict__ rowp, const int* __restrict__ col,
    const float* __restrict__ nd, const float* __restrict__ ns,
    const float* __restrict__ bias,
    float* __restrict__ out_f32,
    __nv_bfloat16* __restrict__ out_hi, __nv_bfloat16* __restrict__ out_lo,
    int n, int mode) {
    int warp = (blockIdx.x * blockDim.x + threadIdx.x) >> 5;
    int lane = threadIdx.x & 31;
    if (warp >= n) return;

    const float4* yrow = (const float4*)(y + (size_t)warp * HDIM);
    float4 acc = yrow[lane];  // self loop

    int s = __ldg(&rowp[warp]);
    int e = __ldg(&rowp[warp + 1]);
    for (int i = s; i < e; i++) {
        int nb = __ldg(&col[i]);
        float4 v = *((const float4*)(y + (size_t)nb * HDIM) + lane);
        acc.x += v.x; acc.y += v.y; acc.z += v.z; acc.w += v.w;
    }
    float sc = nd[warp];
    float4 b = ((const float4*)bias)[lane];
    float4 r;
    r.x = fmaf(acc.x, sc, b.x);
    r.y = fmaf(acc.y, sc, b.y);
    r.z = fmaf(acc.z, sc, b.z);
    r.w = fmaf(acc.w, sc, b.w);
    if (mode) {
        r.x = fmaxf(r.x, 0.f); r.y = fmaxf(r.y, 0.f);
        r.z = fmaxf(r.z, 0.f); r.w = fmaxf(r.w, 0.f);
        float nsv = ns[warp];
        union { ushort4 u; __nv_bfloat16 bb[4]; } H, L;
        split_bf16(r.x * nsv, H.bb[0], L.bb[0]);
        split_bf16(r.y * nsv, H.bb[1], L.bb[1]);
        split_bf16(r.z * nsv, H.bb[2], L.bb[2]);
        split_bf16(r.w * nsv, H.bb[3], L.bb[3]);
        *(ushort4*)&out_hi[(size_t)warp * HDIM + lane * 4] = H.u;
        *(ushort4*)&out_lo[(size_t)warp * HDIM + lane * 4] = L.u;
    } else {
        ((float4*)(out_f32 + (size_t)warp * HDIM))[lane] = r;
    }
}

// ---------------- host orchestration ----------------
static inline int cdiv(int a, int b) { return (a + b - 1) / b; }

extern "C" void kernel_launch(void* const* d_in, const int* in_sizes, int n_in,
                              void* d_out, int out_size) {
    const float* feat_a = (const float*)d_in[0];
    const float* feat_b = (const float*)d_in[1];
    const int* src_a = (const int*)d_in[2];
    const int* dst_a = (const int*)d_in[3];
    const int* src_b = (const int*)d_in[4];
    const int* dst_b = (const int*)d_in[5];
    const float* Wa0 = (const float*)d_in[6];
    const float* ba0 = (const float*)d_in[7];
    const float* Wa1 = (const float*)d_in[8];
    const float* ba1 = (const float*)d_in[9];
    const float* Wb0 = (const float*)d_in[10];
    const float* bb0 = (const float*)d_in[11];
    const float* Wb1 = (const float*)d_in[12];
    const float* bb1 = (const float*)d_in[13];

    const int H = in_sizes[7];                 // 128
    const int DA = in_sizes[6] / H;            // 256
    const int NA = in_sizes[0] / DA;           // 50000
    const int EA = in_sizes[2];                // 600000
    const int DB = in_sizes[10] / H;           // 128
    const int NB = in_sizes[1] / DB;           // 30000
    const int EB = in_sizes[4];                // 300000

    float* out = (float*)d_out;
    float* out_a = out;
    float* out_b = out + (size_t)NA * HDIM;

    __nv_bfloat16 *XhiA, *XloA, *XhiB, *XloB, *Whi, *Wlo;
    float *YA, *YB, *nsA, *ndA, *nsB, *ndB;
    int *cntOutA, *cntInA, *fillA, *rowpA, *colA;
    int *cntOutB, *cntInB, *fillB, *rowpB, *colB;
    cudaGetSymbolAddress((void**)&XhiA, g_XhiA);
    cudaGetSymbolAddress((void**)&XloA, g_XloA);
    cudaGetSymbolAddress((void**)&YA, g_YA);
    cudaGetSymbolAddress((void**)&XhiB, g_XhiB);
    cudaGetSymbolAddress((void**)&XloB, g_XloB);
    cudaGetSymbolAddress((void**)&YB, g_YB);
    cudaGetSymbolAddress((void**)&Whi, g_Whi);
    cudaGetSymbolAddress((void**)&Wlo, g_Wlo);
    cudaGetSymbolAddress((void**)&nsA, g_nsA);
    cudaGetSymbolAddress((void**)&ndA, g_ndA);
    cudaGetSymbolAddress((void**)&nsB, g_nsB);
    cudaGetSymbolAddress((void**)&ndB, g_ndB);
    cudaGetSymbolAddress((void**)&cntOutA, g_cntOutA);
    cudaGetSymbolAddress((void**)&cntInA, g_cntInA);
    cudaGetSymbolAddress((void**)&fillA, g_fillA);
    cudaGetSymbolAddress((void**)&rowpA, g_rowpA);
    cudaGetSymbolAddress((void**)&colA, g_colA);
    cudaGetSymbolAddress((void**)&cntOutB, g_cntOutB);
    cudaGetSymbolAddress((void**)&cntInB, g_cntInB);
    cudaGetSymbolAddress((void**)&fillB, g_fillB);
    cudaGetSymbolAddress((void**)&rowpB, g_rowpB);
    cudaGetSymbolAddress((void**)&colB, g_colB);

    cudaFuncSetAttribute(gemm_bf16_kernel,
                         cudaFuncAttributeMaxDynamicSharedMemorySize, GEMM_SMEM);

    const int T = 256;

    // ---- prep (A + B) ----
    zero_all_kernel<<<cdiv(NA, T), T>>>(cntOutA, cntInA, fillA, NA,
                                        cntOutB, cntInB, fillB, NB);
    count_deg_kernel<<<cdiv(EA, T), T>>>(src_a, dst_a, EA, cntOutA, cntInA);
    count_deg_kernel<<<cdiv(EB, T), T>>>(src_b, dst_b, EB, cntOutB, cntInB);
    norms_kernel<<<cdiv(NA, T), T>>>(cntOutA, cntInA, nsA, ndA, NA);
    norms_kernel<<<cdiv(NB, T), T>>>(cntOutB, cntInB, nsB, ndB, NB);
    scan_kernel<<<1, 1024>>>(cntInA, rowpA, NA);
    scan_kernel<<<1, 1024>>>(cntInB, rowpB, NB);
    csr_fill_kernel<<<cdiv(EA, T), T>>>(src_a, dst_a, EA, rowpA, fillA, colA);
    csr_fill_kernel<<<cdiv(EB, T), T>>>(src_b, dst_b, EB, rowpB, fillB, colB);

    // ===== ntype A =====
    convW_kernel<<<cdiv(DA * H, T), T>>>(Wa0, Whi, Wlo, DA);
    {
        int nq = NA * DA / 4;
        int kqshift = (DA == 256) ? 6 : 5;
        convert_feat_kernel<<<cdiv(nq, T), T>>>(feat_a, nsA, XhiA, XloA, nq, kqshift);
    }
    gemm_bf16_kernel<<<cdiv(NA, 128), 256, GEMM_SMEM>>>(XhiA, XloA, Whi, Wlo, YA, NA, DA);
    aggregate_kernel<<<cdiv(NA * 32, 256), 256>>>(YA, rowpA, colA, ndA, nsA, ba0,
                                                  nullptr, XhiA, XloA, NA, 1);
    convW_kernel<<<cdiv(H * H, T), T>>>(Wa1, Whi, Wlo, H);
    gemm_bf16_kernel<<<cdiv(NA, 128), 256, GEMM_SMEM>>>(XhiA, XloA, Whi, Wlo, YA, NA, H);
    aggregate_kernel<<<cdiv(NA * 32, 256), 256>>>(YA, rowpA, colA, ndA, nsA, ba1,
                                                  out_a, nullptr, nullptr, NA, 0);

    // ===== ntype B =====
    convW_kernel<<<cdiv(DB * H, T), T>>>(Wb0, Whi, Wlo, DB);
    {
        int nq = NB * DB / 4;
        int kqshift = (DB == 256) ? 6 : 5;
        convert_feat_kernel<<<cdiv(nq, T), T>>>(feat_b, nsB, XhiB, XloB, nq, kqshift);
    }
    gemm_bf16_kernel<<<cdiv(NB, 128), 256, GEMM_SMEM>>>(XhiB, XloB, Whi, Wlo, YB, NB, DB);
    aggregate_kernel<<<cdiv(NB * 32, 256), 256>>>(YB, rowpB, colB, ndB, nsB, bb0,
                                                  nullptr, XhiB, XloB, NB, 1);
    convW_kernel<<<cdiv(H * H, T), T>>>(Wb1, Whi, Wlo, H);
    gemm_bf16_kernel<<<cdiv(NB, 128), 256, GEMM_SMEM>>>(XhiB, XloB, Whi, Wlo, YB, NB, H);
    aggregate_kernel<<<cdiv(NB * 32, 256), 256>>>(YB, rowpB, colB, ndB, nsB, bb1,
                                                  out_b, nullptr, nullptr, NB, 0);

    (void)n_in; (void)out_size;
}

// round 6
// speedup vs baseline: 1.8741x; 1.1043x over previous
#include <cuda_runtime.h>
#include <cuda_bf16.h>
#include <cstdint>

#define HDIM 128
#define SPAD 40

// ---------------- static scratch ----------------
#define NA_MAX 50000
#define NB_MAX 30000
#define EA_MAX 600000
#define EB_MAX 300000

__device__ __nv_bfloat16 g_XhiA[NA_MAX * 256];
__device__ __nv_bfloat16 g_XloA[NA_MAX * 256];
__device__ float g_YA[NA_MAX * HDIM];
__device__ __nv_bfloat16 g_XhiB[NB_MAX * HDIM];
__device__ __nv_bfloat16 g_XloB[NB_MAX * HDIM];
__device__ float g_YB[NB_MAX * HDIM];
__device__ __nv_bfloat16 g_Whi[256 * HDIM];   // transposed [N][K]
__device__ __nv_bfloat16 g_Wlo[256 * HDIM];

__device__ int g_cntOutA[NA_MAX];
__device__ int g_cntInA[NA_MAX];
__device__ int g_fillA[NA_MAX];
__device__ int g_rowpA[NA_MAX + 1];
__device__ int g_colA[EA_MAX];
__device__ float g_nsA[NA_MAX];
__device__ float g_ndA[NA_MAX];

__device__ int g_cntOutB[NB_MAX];
__device__ int g_cntInB[NB_MAX];
__device__ int g_fillB[NB_MAX];
__device__ int g_rowpB[NB_MAX + 1];
__device__ int g_colB[EB_MAX];
__device__ float g_nsB[NB_MAX];
__device__ float g_ndB[NB_MAX];

// ---------------- merged graph-prep kernels (A + B in one launch) ----------------
__global__ void zero_all_kernel(int* a0, int* a1, int* a2, int na,
                                int* b0, int* b1, int* b2, int nb) {
    int i = blockIdx.x * blockDim.x + threadIdx.x;
    if (i < na) { a0[i] = 0; a1[i] = 0; a2[i] = 0; }
    if (i < nb) { b0[i] = 0; b1[i] = 0; b2[i] = 0; }
}

__global__ void count_deg_both_kernel(const int* __restrict__ srcA, const int* __restrict__ dstA,
                                      int EA, int* cntOutA, int* cntInA,
                                      const int* __restrict__ srcB, const int* __restrict__ dstB,
                                      int EB, int* cntOutB, int* cntInB) {
    int i = blockIdx.x * blockDim.x + threadIdx.x;
    if (i < EA) {
        atomicAdd(&cntOutA[srcA[i]], 1);
        atomicAdd(&cntInA[dstA[i]], 1);
    }
    if (i < EB) {
        atomicAdd(&cntOutB[srcB[i]], 1);
        atomicAdd(&cntInB[dstB[i]], 1);
    }
}

__global__ void norms_both_kernel(const int* __restrict__ coA, const int* __restrict__ ciA,
                                  float* nsA, float* ndA, int na,
                                  const int* __restrict__ coB, const int* __restrict__ ciB,
                                  float* nsB, float* ndB, int nb) {
    int i = blockIdx.x * blockDim.x + threadIdx.x;
    if (i < na) {
        nsA[i] = rsqrtf((float)(coA[i] + 1));
        ndA[i] = rsqrtf((float)(ciA[i] + 1));
    }
    if (i < nb) {
        nsB[i] = rsqrtf((float)(coB[i] + 1));
        ndB[i] = rsqrtf((float)(ciB[i] + 1));
    }
}

// exclusive scan; block 0 scans (cntA->rowpA), block 1 scans (cntB->rowpB)
__global__ void scan_both_kernel(const int* __restrict__ cntA, int* rowpA, int na,
                                 const int* __restrict__ cntB, int* rowpB, int nb) {
    const int* cnt = (blockIdx.x == 0) ? cntA : cntB;
    int* rowp = (blockIdx.x == 0) ? rowpA : rowpB;
    int n = (blockIdx.x == 0) ? na : nb;

    __shared__ int warpsum[32];
    __shared__ int carry_s;
    const int tid = threadIdx.x;
    const int lane = tid & 31;
    const int wid = tid >> 5;
    if (tid == 0) { carry_s = 0; rowp[0] = 0; }
    __syncthreads();
    for (int base = 0; base < n; base += 1024) {
        int i = base + tid;
        int x = (i < n) ? cnt[i] : 0;
        #pragma unroll
        for (int d = 1; d < 32; d <<= 1) {
            int y = __shfl_up_sync(0xFFFFFFFFu, x, d);
            if (lane >= d) x += y;
        }
        if (lane == 31) warpsum[wid] = x;
        __syncthreads();
        if (wid == 0) {
            int w = warpsum[lane];
            #pragma unroll
            for (int d = 1; d < 32; d <<= 1) {
                int y = __shfl_up_sync(0xFFFFFFFFu, w, d);
                if (lane >= d) w += y;
            }
            warpsum[lane] = w;
        }
        __syncthreads();
        int off = carry_s + (wid ? warpsum[wid - 1] : 0);
        if (i < n) rowp[i + 1] = off + x;
        __syncthreads();
        if (tid == 0) carry_s += warpsum[31];
        __syncthreads();
    }
}

__global__ void csr_fill_both_kernel(const int* __restrict__ srcA, const int* __restrict__ dstA,
                                     int EA, const int* __restrict__ rowpA, int* fillA, int* colA,
                                     const int* __restrict__ srcB, const int* __restrict__ dstB,
                                     int EB, const int* __restrict__ rowpB, int* fillB, int* colB) {
    int i = blockIdx.x * blockDim.x + threadIdx.x;
    if (i < EA) {
        int d = dstA[i];
        int pos = atomicAdd(&fillA[d], 1);
        colA[rowpA[d] + pos] = srcA[i];
    }
    if (i < EB) {
        int d = dstB[i];
        int pos = atomicAdd(&fillB[d], 1);
        colB[rowpB[d] + pos] = srcB[i];
    }
}

// ---------------- bf16 split helpers ----------------
__device__ __forceinline__ void split_bf16(float v, __nv_bfloat16& hi, __nv_bfloat16& lo) {
    hi = __float2bfloat16(v);
    lo = __float2bfloat16(v - __bfloat162float(hi));
}

__global__ void convert_feat_kernel(const float* __restrict__ X, const float* __restrict__ ns,
                                    __nv_bfloat16* __restrict__ Xhi, __nv_bfloat16* __restrict__ Xlo,
                                    int nquads, int kqshift) {
    int q = blockIdx.x * blockDim.x + threadIdx.x;
    if (q >= nquads) return;
    int row = q >> kqshift;
    float s = ns[row];
    float4 v = ((const float4*)X)[q];
    union { ushort4 u; __nv_bfloat16 b[4]; } H, L;
    split_bf16(v.x * s, H.b[0], L.b[0]);
    split_bf16(v.y * s, H.b[1], L.b[1]);
    split_bf16(v.z * s, H.b[2], L.b[2]);
    split_bf16(v.w * s, H.b[3], L.b[3]);
    ((ushort4*)Xhi)[q] = H.u;
    ((ushort4*)Xlo)[q] = L.u;
}

__global__ void convW_kernel(const float* __restrict__ W,
                             __nv_bfloat16* __restrict__ Whi, __nv_bfloat16* __restrict__ Wlo,
                             int K) {
    int idx = blockIdx.x * blockDim.x + threadIdx.x;
    if (idx >= K * HDIM) return;
    int k = idx >> 7;
    int n = idx & 127;
    __nv_bfloat16 hi, lo;
    split_bf16(W[idx], hi, lo);
    Whi[n * K + k] = hi;
    Wlo[n * K + k] = lo;
}

// ---------------- MMA / LDSM / cp.async primitives ----------------
__device__ __forceinline__ void mma_bf16(float& d0, float& d1, float& d2, float& d3,
                                         unsigned a0, unsigned a1, unsigned a2, unsigned a3,
                                         unsigned b0, unsigned b1) {
    asm volatile(
        "mma.sync.aligned.m16n8k16.row.col.f32.bf16.bf16.f32 "
        "{%0,%1,%2,%3}, {%4,%5,%6,%7}, {%8,%9}, {%0,%1,%2,%3};"
        : "+f"(d0), "+f"(d1), "+f"(d2), "+f"(d3)
        : "r"(a0), "r"(a1), "r"(a2), "r"(a3), "r"(b0), "r"(b1));
}

__device__ __forceinline__ void ldsm4(uint32_t addr, unsigned& r0, unsigned& r1,
                                      unsigned& r2, unsigned& r3) {
    asm volatile("ldmatrix.sync.aligned.m8n8.x4.shared.b16 {%0,%1,%2,%3}, [%4];"
                 : "=r"(r0), "=r"(r1), "=r"(r2), "=r"(r3) : "r"(addr));
}

__device__ __forceinline__ void cp16(uint32_t smem_addr, const void* gmem, bool pred) {
    int sz = pred ? 16 : 0;
    asm volatile("cp.async.cg.shared.global [%0], [%1], 16, %2;"
                 :: "r"(smem_addr), "l"(gmem), "r"(sz));
}
__device__ __forceinline__ void cp_commit() {
    asm volatile("cp.async.commit_group;");
}
__device__ __forceinline__ void cp_wait1() {
    asm volatile("cp.async.wait_group 1;");
}

// ---------------- bf16-split tensor-core GEMM ----------------
#define STAGE_ELE (128 * SPAD)
#define STAGE_BYTES (STAGE_ELE * 2)
#define GEMM_SMEM (4 * 2 * STAGE_BYTES)  // 81920 B

__global__ __launch_bounds__(256) void gemm_bf16_kernel(
    const __nv_bfloat16* __restrict__ Ahi, const __nv_bfloat16* __restrict__ Alo,
    const __nv_bfloat16* __restrict__ Bhi, const __nv_bfloat16* __restrict__ Blo,
    float* __restrict__ Y, int M, int K) {
    extern __shared__ __align__(16) char dynsmem[];
    __nv_bfloat16* sAhi = (__nv_bfloat16*)dynsmem;
    __nv_bfloat16* sAlo = sAhi + 2 * STAGE_ELE;
    __nv_bfloat16* sBhi = sAlo + 2 * STAGE_ELE;
    __nv_bfloat16* sBlo = sBhi + 2 * STAGE_ELE;

    const int tid = threadIdx.x;
    const int wid = tid >> 5;
    const int lane = tid & 31;
    const int warpM = wid >> 2;
    const int warpN = wid & 3;
    const int block_row = blockIdx.x * 128;

    float acc[4][4][4];
    #pragma unroll
    for (int i = 0; i < 4; i++)
        #pragma unroll
        for (int j = 0; j < 4; j++)
            #pragma unroll
            for (int c = 0; c < 4; c++) acc[i][j][c] = 0.0f;

    const int r0 = tid >> 2, kc0 = (tid & 3) * 8;
    const int r1 = r0 + 64;
    const int gr0 = block_row + r0;
    const int gr1 = block_row + r1;
    const bool v0 = gr0 < M;
    const bool v1 = gr1 < M;

    const uint32_t bAhi = (uint32_t)__cvta_generic_to_shared(sAhi);
    const uint32_t bAlo = (uint32_t)__cvta_generic_to_shared(sAlo);
    const uint32_t bBhi = (uint32_t)__cvta_generic_to_shared(sBhi);
    const uint32_t bBlo = (uint32_t)__cvta_generic_to_shared(sBlo);

    const uint32_t st_off0 = (uint32_t)(r0 * SPAD + kc0) * 2;
    const uint32_t st_off1 = (uint32_t)(r1 * SPAD + kc0) * 2;

    const int aRow = warpM * 64 + (lane & 15);
    const int aColOff = (lane >> 4) * 8;
    const uint32_t offA = (uint32_t)(aRow * SPAD + aColOff) * 2;
    const int bRow = warpN * 32 + ((lane >> 4) & 1) * 8 + (lane & 7);
    const int bColOff = ((lane >> 3) & 1) * 8;
    const uint32_t offB = (uint32_t)(bRow * SPAD + bColOff) * 2;

    const int ntiles = K >> 5;

    {
        cp16(bAhi + st_off0, &Ahi[(size_t)gr0 * K + kc0], v0);
        cp16(bAlo + st_off0, &Alo[(size_t)gr0 * K + kc0], v0);
        cp16(bAhi + st_off1, &Ahi[(size_t)gr1 * K + kc0], v1);
        cp16(bAlo + st_off1, &Alo[(size_t)gr1 * K + kc0], v1);
        cp16(bBhi + st_off0, &Bhi[(size_t)r0 * K + kc0], true);
        cp16(bBlo + st_off0, &Blo[(size_t)r0 * K + kc0], true);
        cp16(bBhi + st_off1, &Bhi[(size_t)r1 * K + kc0], true);
        cp16(bBlo + st_off1, &Blo[(size_t)r1 * K + kc0], true);
    }
    cp_commit();

    for (int t = 0; t < ntiles; t++) {
        if (t + 1 < ntiles) {
            const int k0 = (t + 1) << 5;
            const uint32_t sb = (uint32_t)((t + 1) & 1) * STAGE_BYTES;
            cp16(bAhi + sb + st_off0, &Ahi[(size_t)gr0 * K + k0 + kc0], v0);
            cp16(bAlo + sb + st_off0, &Alo[(size_t)gr0 * K + k0 + kc0], v0);
            cp16(bAhi + sb + st_off1, &Ahi[(size_t)gr1 * K + k0 + kc0], v1);
            cp16(bAlo + sb + st_off1, &Alo[(size_t)gr1 * K + k0 + kc0], v1);
            cp16(bBhi + sb + st_off0, &Bhi[(size_t)r0 * K + k0 + kc0], true);
            cp16(bBlo + sb + st_off0, &Blo[(size_t)r0 * K + k0 + kc0], true);
            cp16(bBhi + sb + st_off1, &Bhi[(size_t)r1 * K + k0 + kc0], true);
            cp16(bBlo + sb + st_off1, &Blo[(size_t)r1 * K + k0 + kc0], true);
        }
        cp_commit();
        cp_wait1();
        __syncthreads();

        const uint32_t sb = (uint32_t)(t & 1) * STAGE_BYTES;

        #pragma unroll
        for (int kk = 0; kk < 32; kk += 16) {
            unsigned bh[4][2], bl[4][2];
            #pragma unroll
            for (int pair = 0; pair < 2; pair++) {
                const uint32_t ad = sb + offB + (uint32_t)(pair * 16 * SPAD + kk) * 2;
                ldsm4(bBhi + ad, bh[pair * 2][0], bh[pair * 2][1],
                      bh[pair * 2 + 1][0], bh[pair * 2 + 1][1]);
                ldsm4(bBlo + ad, bl[pair * 2][0], bl[pair * 2][1],
                      bl[pair * 2 + 1][0], bl[pair * 2 + 1][1]);
            }
            #pragma unroll
            for (int mt = 0; mt < 4; mt++) {
                const uint32_t ad = sb + offA + (uint32_t)(mt * 16 * SPAD + kk) * 2;
                unsigned a0, a1, a2, a3, l0, l1, l2, l3;
                ldsm4(bAhi + ad, a0, a1, a2, a3);
                ldsm4(bAlo + ad, l0, l1, l2, l3);
                #pragma unroll
                for (int nt = 0; nt < 4; nt++) {
                    mma_bf16(acc[mt][nt][0], acc[mt][nt][1], acc[mt][nt][2], acc[mt][nt][3],
                             a0, a1, a2, a3, bh[nt][0], bh[nt][1]);
                    mma_bf16(acc[mt][nt][0], acc[mt][nt][1], acc[mt][nt][2], acc[mt][nt][3],
                             a0, a1, a2, a3, bl[nt][0], bl[nt][1]);
                    mma_bf16(acc[mt][nt][0], acc[mt][nt][1], acc[mt][nt][2], acc[mt][nt][3],
                             l0, l1, l2, l3, bh[nt][0], bh[nt][1]);
                }
            }
        }
        __syncthreads();
    }

    const int g = lane >> 2;
    const int tg = lane & 3;
    #pragma unroll
    for (int mt = 0; mt < 4; mt++) {
        #pragma unroll
        for (int nt = 0; nt < 4; nt++) {
            int r = block_row + warpM * 64 + mt * 16 + g;
            int c = warpN * 32 + nt * 8 + tg * 2;
            if (r < M) {
                float2 v0m = make_float2(acc[mt][nt][0], acc[mt][nt][1]);
                *(float2*)&Y[(size_t)r * HDIM + c] = v0m;
            }
            if (r + 8 < M) {
                float2 v1m = make_float2(acc[mt][nt][2], acc[mt][nt][3]);
                *(float2*)&Y[(size_t)(r + 8) * HDIM + c] = v1m;
            }
        }
    }
}

// ---------------- aggregation (unroll-4 gather for MLP) ----------------
__global__ __launch_bounds__(256) void aggregate_kernel(
    const float* __restrict__ y,
    const int* __restrict__ rowp, const int* __restrict__ col,
    const float* __restrict__ nd, const float* __restrict__ ns,
    const float* __restrict__ bias,
    float* __restrict__ out_f32,
    __nv_bfloat16* __restrict__ out_hi, __nv_bfloat16* __restrict__ out_lo,
    int n, int mode) {
    int warp = (blockIdx.x * blockDim.x + threadIdx.x) >> 5;
    int lane = threadIdx.x & 31;
    if (warp >= n) return;

    float4 acc = *((const float4*)(y + (size_t)warp * HDIM) + lane);  // self loop

    const int s = __ldg(&rowp[warp]);
    const int e = __ldg(&rowp[warp + 1]);
    int i = s;
    // unrolled by 4: batch index loads, then 4 independent LDG.128 in flight
    for (; i + 4 <= e; i += 4) {
        int nb0 = __ldg(&col[i]);
        int nb1 = __ldg(&col[i + 1]);
        int nb2 = __ldg(&col[i + 2]);
        int nb3 = __ldg(&col[i + 3]);
        float4 v0 = *((const float4*)(y + (size_t)nb0 * HDIM) + lane);
        float4 v1 = *((const float4*)(y + (size_t)nb1 * HDIM) + lane);
        float4 v2 = *((const float4*)(y + (size_t)nb2 * HDIM) + lane);
        float4 v3 = *((const float4*)(y + (size_t)nb3 * HDIM) + lane);
        acc.x += v0.x + v1.x + v2.x + v3.x;
        acc.y += v0.y + v1.y + v2.y + v3.y;
        acc.z += v0.z + v1.z + v2.z + v3.z;
        acc.w += v0.w + v1.w + v2.w + v3.w;
    }
    for (; i < e; i++) {
        int nb = __ldg(&col[i]);
        float4 v = *((const float4*)(y + (size_t)nb * HDIM) + lane);
        acc.x += v.x; acc.y += v.y; acc.z += v.z; acc.w += v.w;
    }

    float sc = nd[warp];
    float4 b = ((const float4*)bias)[lane];
    float4 r;
    r.x = fmaf(acc.x, sc, b.x);
    r.y = fmaf(acc.y, sc, b.y);
    r.z = fmaf(acc.z, sc, b.z);
    r.w = fmaf(acc.w, sc, b.w);
    if (mode) {
        r.x = fmaxf(r.x, 0.f); r.y = fmaxf(r.y, 0.f);
        r.z = fmaxf(r.z, 0.f); r.w = fmaxf(r.w, 0.f);
        float nsv = ns[warp];
        union { ushort4 u; __nv_bfloat16 bb[4]; } H, L;
        split_bf16(r.x * nsv, H.bb[0], L.bb[0]);
        split_bf16(r.y * nsv, H.bb[1], L.bb[1]);
        split_bf16(r.z * nsv, H.bb[2], L.bb[2]);
        split_bf16(r.w * nsv, H.bb[3], L.bb[3]);
        *(ushort4*)&out_hi[(size_t)warp * HDIM + lane * 4] = H.u;
        *(ushort4*)&out_lo[(size_t)warp * HDIM + lane * 4] = L.u;
    } else {
        ((float4*)(out_f32 + (size_t)warp * HDIM))[lane] = r;
    }
}

// ---------------- host orchestration ----------------
static inline int cdiv(int a, int b) { return (a + b - 1) / b; }

extern "C" void kernel_launch(void* const* d_in, const int* in_sizes, int n_in,
                              void* d_out, int out_size) {
    const float* feat_a = (const float*)d_in[0];
    const float* feat_b = (const float*)d_in[1];
    const int* src_a = (const int*)d_in[2];
    const int* dst_a = (const int*)d_in[3];
    const int* src_b = (const int*)d_in[4];
    const int* dst_b = (const int*)d_in[5];
    const float* Wa0 = (const float*)d_in[6];
    const float* ba0 = (const float*)d_in[7];
    const float* Wa1 = (const float*)d_in[8];
    const float* ba1 = (const float*)d_in[9];
    const float* Wb0 = (const float*)d_in[10];
    const float* bb0 = (const float*)d_in[11];
    const float* Wb1 = (const float*)d_in[12];
    const float* bb1 = (const float*)d_in[13];

    const int H = in_sizes[7];
    const int DA = in_sizes[6] / H;
    const int NA = in_sizes[0] / DA;
    const int EA = in_sizes[2];
    const int DB = in_sizes[10] / H;
    const int NB = in_sizes[1] / DB;
    const int EB = in_sizes[4];

    float* out = (float*)d_out;
    float* out_a = out;
    float* out_b = out + (size_t)NA * HDIM;

    __nv_bfloat16 *XhiA, *XloA, *XhiB, *XloB, *Whi, *Wlo;
    float *YA, *YB, *nsA, *ndA, *nsB, *ndB;
    int *cntOutA, *cntInA, *fillA, *rowpA, *colA;
    int *cntOutB, *cntInB, *fillB, *rowpB, *colB;
    cudaGetSymbolAddress((void**)&XhiA, g_XhiA);
    cudaGetSymbolAddress((void**)&XloA, g_XloA);
    cudaGetSymbolAddress((void**)&YA, g_YA);
    cudaGetSymbolAddress((void**)&XhiB, g_XhiB);
    cudaGetSymbolAddress((void**)&XloB, g_XloB);
    cudaGetSymbolAddress((void**)&YB, g_YB);
    cudaGetSymbolAddress((void**)&Whi, g_Whi);
    cudaGetSymbolAddress((void**)&Wlo, g_Wlo);
    cudaGetSymbolAddress((void**)&nsA, g_nsA);
    cudaGetSymbolAddress((void**)&ndA, g_ndA);
    cudaGetSymbolAddress((void**)&nsB, g_nsB);
    cudaGetSymbolAddress((void**)&ndB, g_ndB);
    cudaGetSymbolAddress((void**)&cntOutA, g_cntOutA);
    cudaGetSymbolAddress((void**)&cntInA, g_cntInA);
    cudaGetSymbolAddress((void**)&fillA, g_fillA);
    cudaGetSymbolAddress((void**)&rowpA, g_rowpA);
    cudaGetSymbolAddress((void**)&colA, g_colA);
    cudaGetSymbolAddress((void**)&cntOutB, g_cntOutB);
    cudaGetSymbolAddress((void**)&cntInB, g_cntInB);
    cudaGetSymbolAddress((void**)&fillB, g_fillB);
    cudaGetSymbolAddress((void**)&rowpB, g_rowpB);
    cudaGetSymbolAddress((void**)&colB, g_colB);

    cudaFuncSetAttribute(gemm_bf16_kernel,
                         cudaFuncAttributeMaxDynamicSharedMemorySize, GEMM_SMEM);

    const int T = 256;

    // ---- merged prep ----
    zero_all_kernel<<<cdiv(NA, T), T>>>(cntOutA, cntInA, fillA, NA,
                                        cntOutB, cntInB, fillB, NB);
    count_deg_both_kernel<<<cdiv(EA > EB ? EA : EB, T), T>>>(
        src_a, dst_a, EA, cntOutA, cntInA,
        src_b, dst_b, EB, cntOutB, cntInB);
    norms_both_kernel<<<cdiv(NA > NB ? NA : NB, T), T>>>(
        cntOutA, cntInA, nsA, ndA, NA,
        cntOutB, cntInB, nsB, ndB, NB);
    scan_both_kernel<<<2, 1024>>>(cntInA, rowpA, NA, cntInB, rowpB, NB);
    csr_fill_both_kernel<<<cdiv(EA > EB ? EA : EB, T), T>>>(
        src_a, dst_a, EA, rowpA, fillA, colA,
        src_b, dst_b, EB, rowpB, fillB, colB);

    // ===== ntype A =====
    convW_kernel<<<cdiv(DA * H, T), T>>>(Wa0, Whi, Wlo, DA);
    {
        int nq = NA * DA / 4;
        int kqshift = (DA == 256) ? 6 : 5;
        convert_feat_kernel<<<cdiv(nq, T), T>>>(feat_a, nsA, XhiA, XloA, nq, kqshift);
    }
    gemm_bf16_kernel<<<cdiv(NA, 128), 256, GEMM_SMEM>>>(XhiA, XloA, Whi, Wlo, YA, NA, DA);
    aggregate_kernel<<<cdiv(NA * 32, 256), 256>>>(YA, rowpA, colA, ndA, nsA, ba0,
                                                  nullptr, XhiA, XloA, NA, 1);
    convW_kernel<<<cdiv(H * H, T), T>>>(Wa1, Whi, Wlo, H);
    gemm_bf16_kernel<<<cdiv(NA, 128), 256, GEMM_SMEM>>>(XhiA, XloA, Whi, Wlo, YA, NA, H);
    aggregate_kernel<<<cdiv(NA * 32, 256), 256>>>(YA, rowpA, colA, ndA, nsA, ba1,
                                                  out_a, nullptr, nullptr, NA, 0);

    // ===== ntype B =====
    convW_kernel<<<cdiv(DB * H, T), T>>>(Wb0, Whi, Wlo, DB);
    {
        int nq = NB * DB / 4;
        int kqshift = (DB == 256) ? 6 : 5;
        convert_feat_kernel<<<cdiv(nq, T), T>>>(feat_b, nsB, XhiB, XloB, nq, kqshift);
    }
    gemm_bf16_kernel<<<cdiv(NB, 128), 256, GEMM_SMEM>>>(XhiB, XloB, Whi, Wlo, YB, NB, DB);
    aggregate_kernel<<<cdiv(NB * 32, 256), 256>>>(YB, rowpB, colB, ndB, nsB, bb0,
                                                  nullptr, XhiB, XloB, NB, 1);
    convW_kernel<<<cdiv(H * H, T), T>>>(Wb1, Whi, Wlo, H);
    gemm_bf16_kernel<<<cdiv(NB, 128), 256, GEMM_SMEM>>>(XhiB, XloB, Whi, Wlo, YB, NB, H);
    aggregate_kernel<<<cdiv(NB * 32, 256), 256>>>(YB, rowpB, colB, ndB, nsB, bb1,
                                                  out_b, nullptr, nullptr, NB, 0);

    (void)n_in; (void)out_size;
}

// round 9
// speedup vs baseline: 2.0805x; 1.1101x over previous
#include <cuda_runtime.h>
#include <cuda_bf16.h>
#include <cstdint>

#define HDIM 128
#define SPAD 40

// ---------------- static scratch ----------------
#define NA_MAX 50000
#define NB_MAX 30000
#define EA_MAX 600000
#define EB_MAX 300000

__device__ __nv_bfloat16 g_XhiA[NA_MAX * 256];
__device__ __nv_bfloat16 g_XloA[NA_MAX * 256];
__device__ float g_YA[NA_MAX * HDIM];
__device__ __nv_bfloat16 g_XhiB[NB_MAX * HDIM];
__device__ __nv_bfloat16 g_XloB[NB_MAX * HDIM];
__device__ float g_YB[NB_MAX * HDIM];
__device__ __nv_bfloat16 g_Whi[256 * HDIM];   // transposed [N][K]
__device__ __nv_bfloat16 g_Wlo[256 * HDIM];

__device__ int g_cntOutA[NA_MAX];
__device__ int g_cntInA[NA_MAX];
__device__ int g_fillA[NA_MAX];
__device__ int g_rowpA[NA_MAX + 1];
__device__ int g_colA[EA_MAX];
__device__ float g_nsA[NA_MAX];
__device__ float g_ndA[NA_MAX];

__device__ int g_cntOutB[NB_MAX];
__device__ int g_cntInB[NB_MAX];
__device__ int g_fillB[NB_MAX];
__device__ int g_rowpB[NB_MAX + 1];
__device__ int g_colB[EB_MAX];
__device__ float g_nsB[NB_MAX];
__device__ float g_ndB[NB_MAX];

__device__ int g_bsumA[64];
__device__ int g_bsumB[64];

// ---------------- merged graph-prep kernels (A + B in one launch) ----------------
__global__ void zero_all_kernel(int* a0, int* a1, int* a2, int na,
                                int* b0, int* b1, int* b2, int nb) {
    int i = blockIdx.x * blockDim.x + threadIdx.x;
    if (i < na) { a0[i] = 0; a1[i] = 0; a2[i] = 0; }
    if (i < nb) { b0[i] = 0; b1[i] = 0; b2[i] = 0; }
}

__global__ void count_deg_both_kernel(const int* __restrict__ srcA, const int* __restrict__ dstA,
                                      int EA, int* cntOutA, int* cntInA,
                                      const int* __restrict__ srcB, const int* __restrict__ dstB,
                                      int EB, int* cntOutB, int* cntInB) {
    int i = blockIdx.x * blockDim.x + threadIdx.x;
    if (i < EA) {
        atomicAdd(&cntOutA[srcA[i]], 1);
        atomicAdd(&cntInA[dstA[i]], 1);
    }
    if (i < EB) {
        atomicAdd(&cntOutB[srcB[i]], 1);
        atomicAdd(&cntInB[dstB[i]], 1);
    }
}

__global__ void norms_both_kernel(const int* __restrict__ coA, const int* __restrict__ ciA,
                                  float* nsA, float* ndA, int na,
                                  const int* __restrict__ coB, const int* __restrict__ ciB,
                                  float* nsB, float* ndB, int nb) {
    int i = blockIdx.x * blockDim.x + threadIdx.x;
    if (i < na) {
        nsA[i] = rsqrtf((float)(coA[i] + 1));
        ndA[i] = rsqrtf((float)(ciA[i] + 1));
    }
    if (i < nb) {
        nsB[i] = rsqrtf((float)(coB[i] + 1));
        ndB[i] = rsqrtf((float)(ciB[i] + 1));
    }
}

// ---- multi-block scan, 3 phases ----
// block-local inclusive scan of 1024 values (shuffle + shared combine)
__device__ __forceinline__ int block_scan_1024(int x, int* warpsum) {
    const int tid = threadIdx.x;
    const int lane = tid & 31;
    const int wid = tid >> 5;
    #pragma unroll
    for (int d = 1; d < 32; d <<= 1) {
        int y = __shfl_up_sync(0xFFFFFFFFu, x, d);
        if (lane >= d) x += y;
    }
    if (lane == 31) warpsum[wid] = x;
    __syncthreads();
    if (wid == 0) {
        int w = warpsum[lane];
        #pragma unroll
        for (int d = 1; d < 32; d <<= 1) {
            int y = __shfl_up_sync(0xFFFFFFFFu, w, d);
            if (lane >= d) w += y;
        }
        warpsum[lane] = w;
    }
    __syncthreads();
    return x + (wid ? warpsum[wid - 1] : 0);
}

// phase 1: per-chunk inclusive scan into rowp[i+1]; chunk totals into bsum
__global__ void scan1_kernel(const int* __restrict__ cntA, int* rowpA, int na, int nblkA,
                             const int* __restrict__ cntB, int* rowpB, int nb,
                             int* bsumA, int* bsumB) {
    __shared__ int warpsum[32];
    int blk = blockIdx.x;
    const int* cnt; int* rowp; int n; int* bsum; int cblk;
    if (blk < nblkA) { cnt = cntA; rowp = rowpA; n = na; bsum = bsumA; cblk = blk; }
    else             { cnt = cntB; rowp = rowpB; n = nb; bsum = bsumB; cblk = blk - nblkA; }
    const int tid = threadIdx.x;
    int i = cblk * 1024 + tid;
    int x = (i < n) ? cnt[i] : 0;
    int inc = block_scan_1024(x, warpsum);
    if (i < n) rowp[i + 1] = inc;
    if (tid == 1023) bsum[cblk] = inc;
    if (cblk == 0 && tid == 0) rowp[0] = 0;
}

// phase 2: exclusive-scan the chunk totals in place (block 0 -> A, block 1 -> B)
__global__ void scan2_kernel(int* bsumA, int nblkA, int* bsumB, int nblkB) {
    __shared__ int warpsum[32];
    int* bsum = (blockIdx.x == 0) ? bsumA : bsumB;
    int nblk = (blockIdx.x == 0) ? nblkA : nblkB;
    const int tid = threadIdx.x;
    int x = (tid < nblk) ? bsum[tid] : 0;
    int inc = block_scan_1024(x, warpsum);
    if (tid < nblk) bsum[tid] = inc - x;  // exclusive
}

// phase 3: add chunk offsets
__global__ void scan3_kernel(int* rowpA, int na, int nblkA,
                             int* rowpB, int nb,
                             const int* __restrict__ bsumA, const int* __restrict__ bsumB) {
    int blk = blockIdx.x;
    int* rowp; int n; const int* bsum; int cblk;
    if (blk < nblkA) { rowp = rowpA; n = na; bsum = bsumA; cblk = blk; }
    else             { rowp = rowpB; n = nb; bsum = bsumB; cblk = blk - nblkA; }
    int off = __ldg(&bsum[cblk]);
    int i = cblk * 1024 + threadIdx.x;
    if (i < n) rowp[i + 1] += off;
}

__global__ void csr_fill_both_kernel(const int* __restrict__ srcA, const int* __restrict__ dstA,
                                     int EA, const int* __restrict__ rowpA, int* fillA, int* colA,
                                     const int* __restrict__ srcB, const int* __restrict__ dstB,
                                     int EB, const int* __restrict__ rowpB, int* fillB, int* colB) {
    int i = blockIdx.x * blockDim.x + threadIdx.x;
    if (i < EA) {
        int d = dstA[i];
        int pos = atomicAdd(&fillA[d], 1);
        colA[rowpA[d] + pos] = srcA[i];
    }
    if (i < EB) {
        int d = dstB[i];
        int pos = atomicAdd(&fillB[d], 1);
        colB[rowpB[d] + pos] = srcB[i];
    }
}

// ---------------- bf16 split helpers ----------------
__device__ __forceinline__ void split_bf16(float v, __nv_bfloat16& hi, __nv_bfloat16& lo) {
    hi = __float2bfloat16(v);
    lo = __float2bfloat16(v - __bfloat162float(hi));
}

__global__ void convert_feat_kernel(const float* __restrict__ X, const float* __restrict__ ns,
                                    __nv_bfloat16* __restrict__ Xhi, __nv_bfloat16* __restrict__ Xlo,
                                    int nquads, int kqshift) {
    int q = blockIdx.x * blockDim.x + threadIdx.x;
    if (q >= nquads) return;
    int row = q >> kqshift;
    float s = ns[row];
    float4 v = ((const float4*)X)[q];
    union { ushort4 u; __nv_bfloat16 b[4]; } H, L;
    split_bf16(v.x * s, H.b[0], L.b[0]);
    split_bf16(v.y * s, H.b[1], L.b[1]);
    split_bf16(v.z * s, H.b[2], L.b[2]);
    split_bf16(v.w * s, H.b[3], L.b[3]);
    ((ushort4*)Xhi)[q] = H.u;
    ((ushort4*)Xlo)[q] = L.u;
}

__global__ void convW_kernel(const float* __restrict__ W,
                             __nv_bfloat16* __restrict__ Whi, __nv_bfloat16* __restrict__ Wlo,
                             int K) {
    int idx = blockIdx.x * blockDim.x + threadIdx.x;
    if (idx >= K * HDIM) return;
    int k = idx >> 7;
    int n = idx & 127;
    __nv_bfloat16 hi, lo;
    split_bf16(W[idx], hi, lo);
    Whi[n * K + k] = hi;
    Wlo[n * K + k] = lo;
}

// ---------------- MMA / LDSM / cp.async primitives ----------------
__device__ __forceinline__ void mma_bf16(float& d0, float& d1, float& d2, float& d3,
                                         unsigned a0, unsigned a1, unsigned a2, unsigned a3,
                                         unsigned b0, unsigned b1) {
    asm volatile(
        "mma.sync.aligned.m16n8k16.row.col.f32.bf16.bf16.f32 "
        "{%0,%1,%2,%3}, {%4,%5,%6,%7}, {%8,%9}, {%0,%1,%2,%3};"
        : "+f"(d0), "+f"(d1), "+f"(d2), "+f"(d3)
        : "r"(a0), "r"(a1), "r"(a2), "r"(a3), "r"(b0), "r"(b1));
}

__device__ __forceinline__ void ldsm4(uint32_t addr, unsigned& r0, unsigned& r1,
                                      unsigned& r2, unsigned& r3) {
    asm volatile("ldmatrix.sync.aligned.m8n8.x4.shared.b16 {%0,%1,%2,%3}, [%4];"
                 : "=r"(r0), "=r"(r1), "=r"(r2), "=r"(r3) : "r"(addr));
}

__device__ __forceinline__ void cp16(uint32_t smem_addr, const void* gmem, bool pred) {
    int sz = pred ? 16 : 0;
    asm volatile("cp.async.cg.shared.global [%0], [%1], 16, %2;"
                 :: "r"(smem_addr), "l"(gmem), "r"(sz));
}
__device__ __forceinline__ void cp_commit() {
    asm volatile("cp.async.commit_group;");
}
__device__ __forceinline__ void cp_wait1() {
    asm volatile("cp.async.wait_group 1;");
}

// ---------------- bf16-split tensor-core GEMM ----------------
#define STAGE_ELE (128 * SPAD)
#define STAGE_BYTES (STAGE_ELE * 2)
#define GEMM_SMEM (4 * 2 * STAGE_BYTES)  // 81920 B

__global__ __launch_bounds__(256) void gemm_bf16_kernel(
    const __nv_bfloat16* __restrict__ Ahi, const __nv_bfloat16* __restrict__ Alo,
    const __nv_bfloat16* __restrict__ Bhi, const __nv_bfloat16* __restrict__ Blo,
    float* __restrict__ Y, int M, int K) {
    extern __shared__ __align__(16) char dynsmem[];
    __nv_bfloat16* sAhi = (__nv_bfloat16*)dynsmem;
    __nv_bfloat16* sAlo = sAhi + 2 * STAGE_ELE;
    __nv_bfloat16* sBhi = sAlo + 2 * STAGE_ELE;
    __nv_bfloat16* sBlo = sBhi + 2 * STAGE_ELE;

    const int tid = threadIdx.x;
    const int wid = tid >> 5;
    const int lane = tid & 31;
    const int warpM = wid >> 2;
    const int warpN = wid & 3;
    const int block_row = blockIdx.x * 128;

    float acc[4][4][4];
    #pragma unroll
    for (int i = 0; i < 4; i++)
        #pragma unroll
        for (int j = 0; j < 4; j++)
            #pragma unroll
            for (int c = 0; c < 4; c++) acc[i][j][c] = 0.0f;

    const int r0 = tid >> 2, kc0 = (tid & 3) * 8;
    const int r1 = r0 + 64;
    const int gr0 = block_row + r0;
    const int gr1 = block_row + r1;
    const bool v0 = gr0 < M;
    const bool v1 = gr1 < M;

    const uint32_t bAhi = (uint32_t)__cvta_generic_to_shared(sAhi);
    const uint32_t bAlo = (uint32_t)__cvta_generic_to_shared(sAlo);
    const uint32_t bBhi = (uint32_t)__cvta_generic_to_shared(sBhi);
    const uint32_t bBlo = (uint32_t)__cvta_generic_to_shared(sBlo);

    const uint32_t st_off0 = (uint32_t)(r0 * SPAD + kc0) * 2;
    const uint32_t st_off1 = (uint32_t)(r1 * SPAD + kc0) * 2;

    const int aRow = warpM * 64 + (lane & 15);
    const int aColOff = (lane >> 4) * 8;
    const uint32_t offA = (uint32_t)(aRow * SPAD + aColOff) * 2;
    const int bRow = warpN * 32 + ((lane >> 4) & 1) * 8 + (lane & 7);
    const int bColOff = ((lane >> 3) & 1) * 8;
    const uint32_t offB = (uint32_t)(bRow * SPAD + bColOff) * 2;

    const int ntiles = K >> 5;

    {
        cp16(bAhi + st_off0, &Ahi[(size_t)gr0 * K + kc0], v0);
        cp16(bAlo + st_off0, &Alo[(size_t)gr0 * K + kc0], v0);
        cp16(bAhi + st_off1, &Ahi[(size_t)gr1 * K + kc0], v1);
        cp16(bAlo + st_off1, &Alo[(size_t)gr1 * K + kc0], v1);
        cp16(bBhi + st_off0, &Bhi[(size_t)r0 * K + kc0], true);
        cp16(bBlo + st_off0, &Blo[(size_t)r0 * K + kc0], true);
        cp16(bBhi + st_off1, &Bhi[(size_t)r1 * K + kc0], true);
        cp16(bBlo + st_off1, &Blo[(size_t)r1 * K + kc0], true);
    }
    cp_commit();

    for (int t = 0; t < ntiles; t++) {
        if (t + 1 < ntiles) {
            const int k0 = (t + 1) << 5;
            const uint32_t sb = (uint32_t)((t + 1) & 1) * STAGE_BYTES;
            cp16(bAhi + sb + st_off0, &Ahi[(size_t)gr0 * K + k0 + kc0], v0);
            cp16(bAlo + sb + st_off0, &Alo[(size_t)gr0 * K + k0 + kc0], v0);
            cp16(bAhi + sb + st_off1, &Ahi[(size_t)gr1 * K + k0 + kc0], v1);
            cp16(bAlo + sb + st_off1, &Alo[(size_t)gr1 * K + k0 + kc0], v1);
            cp16(bBhi + sb + st_off0, &Bhi[(size_t)r0 * K + k0 + kc0], true);
            cp16(bBlo + sb + st_off0, &Blo[(size_t)r0 * K + k0 + kc0], true);
            cp16(bBhi + sb + st_off1, &Bhi[(size_t)r1 * K + k0 + kc0], true);
            cp16(bBlo + sb + st_off1, &Blo[(size_t)r1 * K + k0 + kc0], true);
        }
        cp_commit();
        cp_wait1();
        __syncthreads();

        const uint32_t sb = (uint32_t)(t & 1) * STAGE_BYTES;

        #pragma unroll
        for (int kk = 0; kk < 32; kk += 16) {
            unsigned bh[4][2], bl[4][2];
            #pragma unroll
            for (int pair = 0; pair < 2; pair++) {
                const uint32_t ad = sb + offB + (uint32_t)(pair * 16 * SPAD + kk) * 2;
                ldsm4(bBhi + ad, bh[pair * 2][0], bh[pair * 2][1],
                      bh[pair * 2 + 1][0], bh[pair * 2 + 1][1]);
                ldsm4(bBlo + ad, bl[pair * 2][0], bl[pair * 2][1],
                      bl[pair * 2 + 1][0], bl[pair * 2 + 1][1]);
            }
            #pragma unroll
            for (int mt = 0; mt < 4; mt++) {
                const uint32_t ad = sb + offA + (uint32_t)(mt * 16 * SPAD + kk) * 2;
                unsigned a0, a1, a2, a3, l0, l1, l2, l3;
                ldsm4(bAhi + ad, a0, a1, a2, a3);
                ldsm4(bAlo + ad, l0, l1, l2, l3);
                #pragma unroll
                for (int nt = 0; nt < 4; nt++) {
                    mma_bf16(acc[mt][nt][0], acc[mt][nt][1], acc[mt][nt][2], acc[mt][nt][3],
                             a0, a1, a2, a3, bh[nt][0], bh[nt][1]);
                    mma_bf16(acc[mt][nt][0], acc[mt][nt][1], acc[mt][nt][2], acc[mt][nt][3],
                             a0, a1, a2, a3, bl[nt][0], bl[nt][1]);
                    mma_bf16(acc[mt][nt][0], acc[mt][nt][1], acc[mt][nt][2], acc[mt][nt][3],
                             l0, l1, l2, l3, bh[nt][0], bh[nt][1]);
                }
            }
        }
        __syncthreads();
    }

    const int g = lane >> 2;
    const int tg = lane & 3;
    #pragma unroll
    for (int mt = 0; mt < 4; mt++) {
        #pragma unroll
        for (int nt = 0; nt < 4; nt++) {
            int r = block_row + warpM * 64 + mt * 16 + g;
            int c = warpN * 32 + nt * 8 + tg * 2;
            if (r < M) {
                float2 v0m = make_float2(acc[mt][nt][0], acc[mt][nt][1]);
                *(float2*)&Y[(size_t)r * HDIM + c] = v0m;
            }
            if (r + 8 < M) {
                float2 v1m = make_float2(acc[mt][nt][2], acc[mt][nt][3]);
                *(float2*)&Y[(size_t)(r + 8) * HDIM + c] = v1m;
            }
        }
    }
}

// ---------------- aggregation (unroll-4 gather for MLP) ----------------
__global__ __launch_bounds__(256) void aggregate_kernel(
    const float* __restrict__ y,
    const int* __restrict__ rowp, const int* __restrict__ col,
    const float* __restrict__ nd, const float* __restrict__ ns,
    const float* __restrict__ bias,
    float* __restrict__ out_f32,
    __nv_bfloat16* __restrict__ out_hi, __nv_bfloat16* __restrict__ out_lo,
    int n, int mode) {
    int warp = (blockIdx.x * blockDim.x + threadIdx.x) >> 5;
    int lane = threadIdx.x & 31;
    if (warp >= n) return;

    float4 acc = *((const float4*)(y + (size_t)warp * HDIM) + lane);  // self loop

    const int s = __ldg(&rowp[warp]);
    const int e = __ldg(&rowp[warp + 1]);
    int i = s;
    for (; i + 4 <= e; i += 4) {
        int nb0 = __ldg(&col[i]);
        int nb1 = __ldg(&col[i + 1]);
        int nb2 = __ldg(&col[i + 2]);
        int nb3 = __ldg(&col[i + 3]);
        float4 v0 = *((const float4*)(y + (size_t)nb0 * HDIM) + lane);
        float4 v1 = *((const float4*)(y + (size_t)nb1 * HDIM) + lane);
        float4 v2 = *((const float4*)(y + (size_t)nb2 * HDIM) + lane);
        float4 v3 = *((const float4*)(y + (size_t)nb3 * HDIM) + lane);
        acc.x += v0.x + v1.x + v2.x + v3.x;
        acc.y += v0.y + v1.y + v2.y + v3.y;
        acc.z += v0.z + v1.z + v2.z + v3.z;
        acc.w += v0.w + v1.w + v2.w + v3.w;
    }
    for (; i < e; i++) {
        int nb = __ldg(&col[i]);
        float4 v = *((const float4*)(y + (size_t)nb * HDIM) + lane);
        acc.x += v.x; acc.y += v.y; acc.z += v.z; acc.w += v.w;
    }

    float sc = nd[warp];
    float4 b = ((const float4*)bias)[lane];
    float4 r;
    r.x = fmaf(acc.x, sc, b.x);
    r.y = fmaf(acc.y, sc, b.y);
    r.z = fmaf(acc.z, sc, b.z);
    r.w = fmaf(acc.w, sc, b.w);
    if (mode) {
        r.x = fmaxf(r.x, 0.f); r.y = fmaxf(r.y, 0.f);
        r.z = fmaxf(r.z, 0.f); r.w = fmaxf(r.w, 0.f);
        float nsv = ns[warp];
        union { ushort4 u; __nv_bfloat16 bb[4]; } H, L;
        split_bf16(r.x * nsv, H.bb[0], L.bb[0]);
        split_bf16(r.y * nsv, H.bb[1], L.bb[1]);
        split_bf16(r.z * nsv, H.bb[2], L.bb[2]);
        split_bf16(r.w * nsv, H.bb[3], L.bb[3]);
        *(ushort4*)&out_hi[(size_t)warp * HDIM + lane * 4] = H.u;
        *(ushort4*)&out_lo[(size_t)warp * HDIM + lane * 4] = L.u;
    } else {
        ((float4*)(out_f32 + (size_t)warp * HDIM))[lane] = r;
    }
}

// ---------------- host orchestration ----------------
static inline int cdiv(int a, int b) { return (a + b - 1) / b; }

extern "C" void kernel_launch(void* const* d_in, const int* in_sizes, int n_in,
                              void* d_out, int out_size) {
    const float* feat_a = (const float*)d_in[0];
    const float* feat_b = (const float*)d_in[1];
    const int* src_a = (const int*)d_in[2];
    const int* dst_a = (const int*)d_in[3];
    const int* src_b = (const int*)d_in[4];
    const int* dst_b = (const int*)d_in[5];
    const float* Wa0 = (const float*)d_in[6];
    const float* ba0 = (const float*)d_in[7];
    const float* Wa1 = (const float*)d_in[8];
    const float* ba1 = (const float*)d_in[9];
    const float* Wb0 = (const float*)d_in[10];
    const float* bb0 = (const float*)d_in[11];
    const float* Wb1 = (const float*)d_in[12];
    const float* bb1 = (const float*)d_in[13];

    const int H = in_sizes[7];
    const int DA = in_sizes[6] / H;
    const int NA = in_sizes[0] / DA;
    const int EA = in_sizes[2];
    const int DB = in_sizes[10] / H;
    const int NB = in_sizes[1] / DB;
    const int EB = in_sizes[4];

    float* out = (float*)d_out;
    float* out_a = out;
    float* out_b = out + (size_t)NA * HDIM;

    __nv_bfloat16 *XhiA, *XloA, *XhiB, *XloB, *Whi, *Wlo;
    float *YA, *YB, *nsA, *ndA, *nsB, *ndB;
    int *cntOutA, *cntInA, *fillA, *rowpA, *colA;
    int *cntOutB, *cntInB, *fillB, *rowpB, *colB;
    int *bsumA, *bsumB;
    cudaGetSymbolAddress((void**)&XhiA, g_XhiA);
    cudaGetSymbolAddress((void**)&XloA, g_XloA);
    cudaGetSymbolAddress((void**)&YA, g_YA);
    cudaGetSymbolAddress((void**)&XhiB, g_XhiB);
    cudaGetSymbolAddress((void**)&XloB, g_XloB);
    cudaGetSymbolAddress((void**)&YB, g_YB);
    cudaGetSymbolAddress((void**)&Whi, g_Whi);
    cudaGetSymbolAddress((void**)&Wlo, g_Wlo);
    cudaGetSymbolAddress((void**)&nsA, g_nsA);
    cudaGetSymbolAddress((void**)&ndA, g_ndA);
    cudaGetSymbolAddress((void**)&nsB, g_nsB);
    cudaGetSymbolAddress((void**)&ndB, g_ndB);
    cudaGetSymbolAddress((void**)&cntOutA, g_cntOutA);
    cudaGetSymbolAddress((void**)&cntInA, g_cntInA);
    cudaGetSymbolAddress((void**)&fillA, g_fillA);
    cudaGetSymbolAddress((void**)&rowpA, g_rowpA);
    cudaGetSymbolAddress((void**)&colA, g_colA);
    cudaGetSymbolAddress((void**)&cntOutB, g_cntOutB);
    cudaGetSymbolAddress((void**)&cntInB, g_cntInB);
    cudaGetSymbolAddress((void**)&fillB, g_fillB);
    cudaGetSymbolAddress((void**)&rowpB, g_rowpB);
    cudaGetSymbolAddress((void**)&colB, g_colB);
    cudaGetSymbolAddress((void**)&bsumA, g_bsumA);
    cudaGetSymbolAddress((void**)&bsumB, g_bsumB);

    cudaFuncSetAttribute(gemm_bf16_kernel,
                         cudaFuncAttributeMaxDynamicSharedMemorySize, GEMM_SMEM);

    const int T = 256;
    const int nblkA = cdiv(NA, 1024);
    const int nblkB = cdiv(NB, 1024);

    // ---- merged prep ----
    zero_all_kernel<<<cdiv(NA, T), T>>>(cntOutA, cntInA, fillA, NA,
                                        cntOutB, cntInB, fillB, NB);
    count_deg_both_kernel<<<cdiv(EA > EB ? EA : EB, T), T>>>(
        src_a, dst_a, EA, cntOutA, cntInA,
        src_b, dst_b, EB, cntOutB, cntInB);
    norms_both_kernel<<<cdiv(NA > NB ? NA : NB, T), T>>>(
        cntOutA, cntInA, nsA, ndA, NA,
        cntOutB, cntInB, nsB, ndB, NB);
    scan1_kernel<<<nblkA + nblkB, 1024>>>(cntInA, rowpA, NA, nblkA,
                                          cntInB, rowpB, NB, bsumA, bsumB);
    scan2_kernel<<<2, 1024>>>(bsumA, nblkA, bsumB, nblkB);
    scan3_kernel<<<nblkA + nblkB, 1024>>>(rowpA, NA, nblkA, rowpB, NB, bsumA, bsumB);
    csr_fill_both_kernel<<<cdiv(EA > EB ? EA : EB, T), T>>>(
        src_a, dst_a, EA, rowpA, fillA, colA,
        src_b, dst_b, EB, rowpB, fillB, colB);

    // ===== ntype A =====
    convW_kernel<<<cdiv(DA * H, T), T>>>(Wa0, Whi, Wlo, DA);
    {
        int nq = NA * DA / 4;
        int kqshift = (DA == 256) ? 6 : 5;
        convert_feat_kernel<<<cdiv(nq, T), T>>>(feat_a, nsA, XhiA, XloA, nq, kqshift);
    }
    gemm_bf16_kernel<<<cdiv(NA, 128), 256, GEMM_SMEM>>>(XhiA, XloA, Whi, Wlo, YA, NA, DA);
    aggregate_kernel<<<cdiv(NA * 32, 256), 256>>>(YA, rowpA, colA, ndA, nsA, ba0,
                                                  nullptr, XhiA, XloA, NA, 1);
    convW_kernel<<<cdiv(H * H, T), T>>>(Wa1, Whi, Wlo, H);
    gemm_bf16_kernel<<<cdiv(NA, 128), 256, GEMM_SMEM>>>(XhiA, XloA, Whi, Wlo, YA, NA, H);
    aggregate_kernel<<<cdiv(NA * 32, 256), 256>>>(YA, rowpA, colA, ndA, nsA, ba1,
                                                  out_a, nullptr, nullptr, NA, 0);

    // ===== ntype B =====
    convW_kernel<<<cdiv(DB * H, T), T>>>(Wb0, Whi, Wlo, DB);
    {
        int nq = NB * DB / 4;
        int kqshift = (DB == 256) ? 6 : 5;
        convert_feat_kernel<<<cdiv(nq, T), T>>>(feat_b, nsB, XhiB, XloB, nq, kqshift);
    }
    gemm_bf16_kernel<<<cdiv(NB, 128), 256, GEMM_SMEM>>>(XhiB, XloB, Whi, Wlo, YB, NB, DB);
    aggregate_kernel<<<cdiv(NB * 32, 256), 256>>>(YB, rowpB, colB, ndB, nsB, bb0,
                                                  nullptr, XhiB, XloB, NB, 1);
    convW_kernel<<<cdiv(H * H, T), T>>>(Wb1, Whi, Wlo, H);
    gemm_bf16_kernel<<<cdiv(NB, 128), 256, GEMM_SMEM>>>(XhiB, XloB, Whi, Wlo, YB, NB, H);
    aggregate_kernel<<<cdiv(NB * 32, 256), 256>>>(YB, rowpB, colB, ndB, nsB, bb1,
                                                  out_b, nullptr, nullptr, NB, 0);

    (void)n_in; (void)out_size;
}